// round 14
// baseline (speedup 1.0000x reference)
#include <cuda_runtime.h>
#include <cuda_bf16.h>
#include <cstdint>

#define BATCH 32
#define NTOK  4096
#define DIM   256
#define HEADS 4
#define DH    64
#define SLOTS 8
#define ITERS 3
#define SPLIT 8   // token chunks per (b,h) in attention

// ---------------- scratch (static device memory; no allocations) ----------------
__device__ float g_xln[BATCH * NTOK * DIM];             // LayerNorm'd inputs
__device__ __nv_bfloat16 g_k[BATCH * HEADS * NTOK * DH]; // (b,h,n,dh) bf16
__device__ __nv_bfloat16 g_v[BATCH * HEADS * NTOK * DH]; // (b,h,n,dh) bf16
__device__ float g_q[BATCH * HEADS * SLOTS * DH];       // (b,h,s,dh)
__device__ float g_slots[BATCH * SLOTS * DIM];          // current slots
__device__ float g_U[SPLIT][BATCH * HEADS * SLOTS * DH];// partial weighted V sums
__device__ float g_Z[SPLIT][BATCH * HEADS * SLOTS];     // partial attn mass
// transposed bf16 hi/lo weights: [kv][n (256)][k (256)]
__device__ __nv_bfloat16 g_bhi[2 * 256 * 256];
__device__ __nv_bfloat16 g_blo[2 * 256 * 256];

// ---------------- mma.sync helpers (base sm_103 PTX, no "a" features) ----------
__device__ __forceinline__ uint32_t smem_to_u32(const void* p) {
    uint32_t a;
    asm("{ .reg .u64 t; cvta.to.shared.u64 t, %1; cvt.u32.u64 %0, t; }" : "=r"(a) : "l"(p));
    return a;
}
__device__ __forceinline__ void ldsm_x4(uint32_t* r, uint32_t addr) {
    asm volatile("ldmatrix.sync.aligned.m8n8.x4.shared.b16 {%0,%1,%2,%3}, [%4];"
        : "=r"(r[0]), "=r"(r[1]), "=r"(r[2]), "=r"(r[3]) : "r"(addr));
}
__device__ __forceinline__ void ldsm_x2(uint32_t* r, uint32_t addr) {
    asm volatile("ldmatrix.sync.aligned.m8n8.x2.shared.b16 {%0,%1}, [%2];"
        : "=r"(r[0]), "=r"(r[1]) : "r"(addr));
}
__device__ __forceinline__ void mma16816(float* c, const uint32_t* a, const uint32_t* b) {
    asm volatile("mma.sync.aligned.m16n8k16.row.col.f32.bf16.bf16.f32 "
        "{%0,%1,%2,%3}, {%4,%5,%6,%7}, {%8,%9}, {%0,%1,%2,%3};"
        : "+f"(c[0]), "+f"(c[1]), "+f"(c[2]), "+f"(c[3])
        : "r"(a[0]), "r"(a[1]), "r"(a[2]), "r"(a[3]), "r"(b[0]), "r"(b[1]));
}
// XOR swizzle: rows of 128B, 16B chunks, chunk ^= (row & 7)
__device__ __forceinline__ uint32_t swz(uint32_t row, uint32_t kbyte) {
    return row * 128 + ((((kbyte >> 4) ^ (row & 7)) << 4) | (kbyte & 15));
}

// ---------------- slot init: Threefry2x32, JAX partitionable path, key(42) ------
__device__ __forceinline__ unsigned rotl32(unsigned x, int r) {
    return __funnelshift_l(x, x, r);
}

__global__ __launch_bounds__(256) void k_init_slots(const float* __restrict__ mu,
                                                    const float* __restrict__ lsig) {
    unsigned idx = blockIdx.x * blockDim.x + threadIdx.x;  // 0..65535
    if (idx >= 65536u) return;
    const unsigned K0 = 0u, K1 = 42u, K2 = 0x1BD11BDAu ^ 0u ^ 42u;
    unsigned x0 = 0u, x1 = idx;
    x0 += K0; x1 += K1;
#define TFR(r) { x0 += x1; x1 = rotl32(x1, r); x1 ^= x0; }
    TFR(13) TFR(15) TFR(26) TFR(6)
    x0 += K1; x1 += K2 + 1u;
    TFR(17) TFR(29) TFR(16) TFR(24)
    x0 += K2; x1 += K0 + 2u;
    TFR(13) TFR(15) TFR(26) TFR(6)
    x0 += K0; x1 += K1 + 3u;
    TFR(17) TFR(29) TFR(16) TFR(24)
    x0 += K1; x1 += K2 + 4u;
    TFR(13) TFR(15) TFR(26) TFR(6)
    x0 += K2; x1 += K0 + 5u;
#undef TFR
    unsigned bits = x0 ^ x1;
    const float LO = -0.99999994f;
    float f = __uint_as_float((bits >> 9) | 0x3F800000u) - 1.0f;
    float u = fmaxf(LO, f * 2.0f + LO);
    float nz = 1.41421356237309515f * erfinvf(u);
    int d = idx & 255;
    g_slots[idx] = mu[d] + expf(lsig[d]) * nz;
}

// ---------------- LayerNorm of inputs: one WARP per row, no block barriers ------
__global__ __launch_bounds__(256) void k_ln_in(const float* __restrict__ x,
                                               const float* __restrict__ w,
                                               const float* __restrict__ b) {
    const int wid = threadIdx.x >> 5, lane = threadIdx.x & 31;
    const int row = blockIdx.x * 8 + wid;
    const float* src = x + (size_t)row * DIM + lane * 8;
    float4 a0 = *reinterpret_cast<const float4*>(src);
    float4 a1 = *reinterpret_cast<const float4*>(src + 4);
    float s = a0.x + a0.y + a0.z + a0.w + a1.x + a1.y + a1.z + a1.w;
#pragma unroll
    for (int o = 16; o; o >>= 1) s += __shfl_xor_sync(~0u, s, o);
    float mean = s * (1.0f / 256.0f);
    float d0 = a0.x - mean, d1 = a0.y - mean, d2 = a0.z - mean, d3 = a0.w - mean;
    float d4 = a1.x - mean, d5 = a1.y - mean, d6 = a1.z - mean, d7 = a1.w - mean;
    float s2 = d0*d0 + d1*d1 + d2*d2 + d3*d3 + d4*d4 + d5*d5 + d6*d6 + d7*d7;
#pragma unroll
    for (int o = 16; o; o >>= 1) s2 += __shfl_xor_sync(~0u, s2, o);
    float rs = rsqrtf(s2 * (1.0f / 256.0f) + 1e-5f);
    const float4 w0 = *reinterpret_cast<const float4*>(w + lane * 8);
    const float4 w1 = *reinterpret_cast<const float4*>(w + lane * 8 + 4);
    const float4 b0 = *reinterpret_cast<const float4*>(b + lane * 8);
    const float4 b1 = *reinterpret_cast<const float4*>(b + lane * 8 + 4);
    float4 o0, o1;
    o0.x = d0 * rs * w0.x + b0.x; o0.y = d1 * rs * w0.y + b0.y;
    o0.z = d2 * rs * w0.z + b0.z; o0.w = d3 * rs * w0.w + b0.w;
    o1.x = d4 * rs * w1.x + b1.x; o1.y = d5 * rs * w1.y + b1.y;
    o1.z = d6 * rs * w1.z + b1.z; o1.w = d7 * rs * w1.w + b1.w;
    float* dst = g_xln + (size_t)row * DIM + lane * 8;
    *reinterpret_cast<float4*>(dst) = o0;
    *reinterpret_cast<float4*>(dst + 4) = o1;
}

// ---------------- weight prep: W^T -> bf16 hi/lo ----------------
__global__ __launch_bounds__(256) void k_prep_w(const float* __restrict__ Wk,
                                                const float* __restrict__ Wv) {
    int idx = blockIdx.x * 256 + threadIdx.x;   // 0..131071
    int kv = idx >> 16;
    int rest = idx & 65535;
    int n = rest >> 8, k = rest & 255;
    float w = (kv ? Wv : Wk)[k * 256 + n];
    __nv_bfloat16 h = __float2bfloat16(w);
    __nv_bfloat16 l = __float2bfloat16(w - __bfloat162float(h));
    g_bhi[idx] = h;
    g_blo[idx] = l;
}

// ---------------- K/V GEMM via mma.sync bf16 hi/lo split (R10 config) ----------
#define SM_AHI 0
#define SM_ALO 16384
#define SM_BHI 32768
#define SM_BLO 49152
#define SM_TOTAL 65536

__global__ __launch_bounds__(256) void k_gemm_kv_mma() {
    extern __shared__ __align__(128) char sm[];
    const int tid = threadIdx.x, wid = tid >> 5, lane = tid & 31;
    const int m0 = blockIdx.x * 128;
    const int nb = blockIdx.y;
    const int kv = nb >> 1;
    const int nloc0 = (nb & 1) * 128;
    const uint32_t smb = smem_to_u32(sm);

    const int wm = (wid >> 2) * 64;
    const int wn = (wid & 3) * 32;

    float acc[4][4][4];
#pragma unroll
    for (int i = 0; i < 4; i++)
#pragma unroll
        for (int j = 0; j < 4; j++)
#pragma unroll
            for (int t = 0; t < 4; t++) acc[i][j][t] = 0.f;

    const int ar = tid >> 1, ah = (tid & 1) * 32;
    const int brow = tid >> 1, bkh = (tid & 1) * 32;
    const float* asrc = &g_xln[(size_t)(m0 + ar) * 256 + ah];
    const __nv_bfloat16* bhsrc = &g_bhi[(size_t)(kv * 256 + nloc0 + brow) * 256 + bkh];
    const __nv_bfloat16* blsrc = &g_blo[(size_t)(kv * 256 + nloc0 + brow) * 256 + bkh];

    const int rowA = wm + (lane & 15);
    const int colAsel = (lane >> 4) * 8;
    const int rowB = wn + (lane & 7);
    const int colBsel = ((lane >> 3) & 1) * 8;

    for (int c = 0; c < 4; c++) {
#pragma unroll
        for (int i = 0; i < 8; i++) {
            float4 a = *reinterpret_cast<const float4*>(asrc + c * 64 + i * 4);
            __nv_bfloat162 h01 = __floats2bfloat162_rn(a.x, a.y);
            __nv_bfloat162 h23 = __floats2bfloat162_rn(a.z, a.w);
            float lx = a.x - __bfloat162float(h01.x);
            float ly = a.y - __bfloat162float(h01.y);
            float lz = a.z - __bfloat162float(h23.x);
            float lw = a.w - __bfloat162float(h23.y);
            __nv_bfloat162 l01 = __floats2bfloat162_rn(lx, ly);
            __nv_bfloat162 l23 = __floats2bfloat162_rn(lz, lw);
            uint32_t sw = swz(ar, (ah + i * 4) * 2);
            uint2 hv, lv;
            hv.x = *reinterpret_cast<uint32_t*>(&h01);
            hv.y = *reinterpret_cast<uint32_t*>(&h23);
            lv.x = *reinterpret_cast<uint32_t*>(&l01);
            lv.y = *reinterpret_cast<uint32_t*>(&l23);
            *reinterpret_cast<uint2*>(sm + SM_AHI + sw) = hv;
            *reinterpret_cast<uint2*>(sm + SM_ALO + sw) = lv;
        }
#pragma unroll
        for (int i = 0; i < 4; i++) {
            uint4 hv = *reinterpret_cast<const uint4*>(bhsrc + c * 64 + i * 8);
            uint4 lv = *reinterpret_cast<const uint4*>(blsrc + c * 64 + i * 8);
            uint32_t sw = swz(brow, (bkh + i * 8) * 2);
            *reinterpret_cast<uint4*>(sm + SM_BHI + sw) = hv;
            *reinterpret_cast<uint4*>(sm + SM_BLO + sw) = lv;
        }
        __syncthreads();

#pragma unroll
        for (int kk = 0; kk < 64; kk += 16) {
            uint32_t Af[4][4], Bh[4][2], Bl[4][2];
            const uint32_t colA2 = (kk + colAsel) * 2;
            const uint32_t colB2 = (kk + colBsel) * 2;
#pragma unroll
            for (int mf = 0; mf < 4; mf++)
                ldsm_x4(Af[mf], smb + SM_AHI + swz(rowA + mf * 16, colA2));
#pragma unroll
            for (int nf = 0; nf < 4; nf++)
                ldsm_x2(Bh[nf], smb + SM_BHI + swz(rowB + nf * 8, colB2));
#pragma unroll
            for (int mf = 0; mf < 4; mf++)
#pragma unroll
                for (int nf = 0; nf < 4; nf++)
                    mma16816(acc[mf][nf], Af[mf], Bh[nf]);
#pragma unroll
            for (int nf = 0; nf < 4; nf++)
                ldsm_x2(Bl[nf], smb + SM_BLO + swz(rowB + nf * 8, colB2));
#pragma unroll
            for (int mf = 0; mf < 4; mf++)
#pragma unroll
                for (int nf = 0; nf < 4; nf++)
                    mma16816(acc[mf][nf], Af[mf], Bl[nf]);
#pragma unroll
            for (int mf = 0; mf < 4; mf++)
                ldsm_x4(Af[mf], smb + SM_ALO + swz(rowA + mf * 16, colA2));
#pragma unroll
            for (int mf = 0; mf < 4; mf++)
#pragma unroll
                for (int nf = 0; nf < 4; nf++)
                    mma16816(acc[mf][nf], Af[mf], Bh[nf]);
        }
        __syncthreads();
    }

    const int g = lane >> 2, tg = lane & 3;
#pragma unroll
    for (int mf = 0; mf < 4; mf++) {
#pragma unroll
        for (int nf = 0; nf < 4; nf++) {
            int col = nb * 128 + wn + nf * 8 + tg * 2;
            __nv_bfloat16* buf = (col < 256) ? g_k : g_v;
            int c8 = col & 255;
            int h = c8 >> 6, dh = c8 & 63;
            int m = m0 + wm + mf * 16 + g;
            int b = m >> 12, n = m & 4095;
            __nv_bfloat16* dst = buf + (size_t)(((b * HEADS + h) * NTOK) + n) * DH + dh;
            __nv_bfloat162 lo = __floats2bfloat162_rn(acc[mf][nf][0], acc[mf][nf][1]);
            __nv_bfloat162 hi2 = __floats2bfloat162_rn(acc[mf][nf][2], acc[mf][nf][3]);
            *reinterpret_cast<uint32_t*>(dst) = *reinterpret_cast<uint32_t*>(&lo);
            *reinterpret_cast<uint32_t*>(dst + 8 * DH) = *reinterpret_cast<uint32_t*>(&hi2);
        }
    }
}

// ---------------- slot LN + Q projection (iteration 0 only) ----------------
__global__ __launch_bounds__(256) void k_slot_q(const float* __restrict__ Wq,
                                                const float* __restrict__ w,
                                                const float* __restrict__ b) {
    int row = blockIdx.x;   // b*8 + s
    int j = threadIdx.x;
    __shared__ float sln[256];
    __shared__ float red[8];
    float v = g_slots[row * DIM + j];
    float s = v;
#pragma unroll
    for (int o = 16; o; o >>= 1) s += __shfl_xor_sync(~0u, s, o);
    if ((j & 31) == 0) red[j >> 5] = s;
    __syncthreads();
    float tot = 0.f;
#pragma unroll
    for (int t = 0; t < 8; t++) tot += red[t];
    float mean = tot * (1.0f / 256.0f);
    __syncthreads();
    float dv = v - mean;
    float s2 = dv * dv;
#pragma unroll
    for (int o = 16; o; o >>= 1) s2 += __shfl_xor_sync(~0u, s2, o);
    if ((j & 31) == 0) red[j >> 5] = s2;
    __syncthreads();
    float tv = 0.f;
#pragma unroll
    for (int t = 0; t < 8; t++) tv += red[t];
    sln[j] = dv * rsqrtf(tv * (1.0f / 256.0f) + 1e-5f) * w[j] + b[j];
    __syncthreads();
    float acc = 0.f;
    for (int i = 0; i < 256; i++) acc += sln[i] * Wq[i * 256 + j];
    int bb = row >> 3, sl = row & 7, h = j >> 6, dh = j & 63;
    g_q[(((bb * HEADS + h) * SLOTS) + sl) * DH + dh] = acc;
}

// ---------------- fused attention v3: vectorized LDS, token-pair per lane ------
// grid (SPLIT, HEADS, BATCH), 256 threads. Warp = slot i; lane owns tokens 2l,2l+1
// for dt/pt/softmax, and dims 2l,2l+1 for U.
__global__ __launch_bounds__(256) void k_attn() {
    const int chunk = blockIdx.x, h = blockIdx.y, b = blockIdx.z;
    const int tid = threadIdx.x;
    const int i = tid >> 5;   // slot (warp)
    const int l = tid & 31;   // lane
    const int bh = b * HEADS + h;

    __shared__ float q[8][64];
    __shared__ float kT[64][66];           // [d][token], float2-friendly
    __shared__ __align__(16) float vb[64][64];
    __shared__ __align__(16) float dt_s[8][68];  // [slot][token]
    __shared__ __align__(16) float pt_s[8][68];

    for (int idx = tid; idx < 512; idx += 256)
        q[idx >> 6][idx & 63] = g_q[bh * 512 + idx];

    const __nv_bfloat16* kbase = &g_k[(size_t)bh * NTOK * DH];
    const __nv_bfloat16* vbase = &g_v[(size_t)bh * NTOK * DH];
    const int TOK = NTOK / SPLIT;   // 512
    const int NT = TOK / 64;        // 8
    const int j0base = chunk * TOK;

    float u0 = 0.f, u1 = 0.f, zacc = 0.f;

    // prefetch tile 0
    uint4 kr[2], vr[2];
#pragma unroll
    for (int qq = 0; qq < 2; qq++) {
        int id = tid + qq * 256;
        int t = id >> 3, d8 = (id & 7) * 8;
        kr[qq] = *reinterpret_cast<const uint4*>(kbase + (size_t)(j0base + t) * DH + d8);
        vr[qq] = *reinterpret_cast<const uint4*>(vbase + (size_t)(j0base + t) * DH + d8);
    }
    __syncthreads();   // q ready

    for (int tile = 0; tile < NT; tile++) {
        // store prefetched regs to smem (bf16 -> fp32)
#pragma unroll
        for (int qq = 0; qq < 2; qq++) {
            int id = tid + qq * 256;
            int t = id >> 3, d8 = (id & 7) * 8;
            const __nv_bfloat162* kp = reinterpret_cast<const __nv_bfloat162*>(&kr[qq]);
            const __nv_bfloat162* vp = reinterpret_cast<const __nv_bfloat162*>(&vr[qq]);
#pragma unroll
            for (int e = 0; e < 4; e++) {
                float2 kf = __bfloat1622float2(kp[e]);
                kT[d8 + 2 * e][t]     = kf.x;
                kT[d8 + 2 * e + 1][t] = kf.y;
            }
            float2 f0 = __bfloat1622float2(vp[0]);
            float2 f1 = __bfloat1622float2(vp[1]);
            float2 f2 = __bfloat1622float2(vp[2]);
            float2 f3 = __bfloat1622float2(vp[3]);
            float4 v04 = {f0.x, f0.y, f1.x, f1.y};
            float4 v14 = {f2.x, f2.y, f3.x, f3.y};
            *reinterpret_cast<float4*>(&vb[t][d8])     = v04;
            *reinterpret_cast<float4*>(&vb[t][d8 + 4]) = v14;
        }
        __syncthreads();

        // prefetch next tile (overlaps compute)
        if (tile + 1 < NT) {
            const int j0n = j0base + (tile + 1) * 64;
#pragma unroll
            for (int qq = 0; qq < 2; qq++) {
                int id = tid + qq * 256;
                int t = id >> 3, d8 = (id & 7) * 8;
                kr[qq] = *reinterpret_cast<const uint4*>(kbase + (size_t)(j0n + t) * DH + d8);
                vr[qq] = *reinterpret_cast<const uint4*>(vbase + (size_t)(j0n + t) * DH + d8);
            }
        }

        // dots: slot i vs tokens 2l, 2l+1 (float2 K reads, float4 q broadcast)
        float a0 = 0.f, a1 = 0.f;
#pragma unroll
        for (int d = 0; d < 64; d += 4) {
            float4 q4 = *reinterpret_cast<const float4*>(&q[i][d]);
            float2 k0 = *reinterpret_cast<const float2*>(&kT[d][2 * l]);
            float2 k1 = *reinterpret_cast<const float2*>(&kT[d + 1][2 * l]);
            float2 k2 = *reinterpret_cast<const float2*>(&kT[d + 2][2 * l]);
            float2 k3 = *reinterpret_cast<const float2*>(&kT[d + 3][2 * l]);
            a0 += q4.x * k0.x + q4.y * k1.x + q4.z * k2.x + q4.w * k3.x;
            a1 += q4.x * k0.y + q4.y * k1.y + q4.z * k2.y + q4.w * k3.y;
        }
        float2 dpair = {a0 * 0.125f, a1 * 0.125f};
        *reinterpret_cast<float2*>(&dt_s[i][2 * l]) = dpair;
        __syncthreads();

        // softmax over slots for tokens 2l, 2l+1
        {
            float2 dv[8];
#pragma unroll
            for (int jj = 0; jj < 8; jj++)
                dv[jj] = *reinterpret_cast<const float2*>(&dt_s[jj][2 * l]);
            float m0 = dv[0].x, m1 = dv[0].y;
#pragma unroll
            for (int jj = 1; jj < 8; jj++) {
                m0 = fmaxf(m0, dv[jj].x);
                m1 = fmaxf(m1, dv[jj].y);
            }
            float s0 = 0.f, s1 = 0.f;
#pragma unroll
            for (int jj = 0; jj < 8; jj++) {
                s0 += __expf(dv[jj].x - m0);
                s1 += __expf(dv[jj].y - m1);
            }
            float p0 = __expf(dv[i].x - m0) / s0 + 1e-8f;
            float p1 = __expf(dv[i].y - m1) / s1 + 1e-8f;
            zacc += p0 + p1;
            float2 ppair = {p0, p1};
            *reinterpret_cast<float2*>(&pt_s[i][2 * l]) = ppair;
        }
        __syncthreads();

        // update: U[i][2l..2l+1] += sum_t p[i][t] * v[t][:] (float4 p broadcast)
#pragma unroll
        for (int t = 0; t < 64; t += 4) {
            float4 p4 = *reinterpret_cast<const float4*>(&pt_s[i][t]);
            float2 v0 = *reinterpret_cast<const float2*>(&vb[t][2 * l]);
            float2 v1 = *reinterpret_cast<const float2*>(&vb[t + 1][2 * l]);
            float2 v2 = *reinterpret_cast<const float2*>(&vb[t + 2][2 * l]);
            float2 v3 = *reinterpret_cast<const float2*>(&vb[t + 3][2 * l]);
            u0 += p4.x * v0.x + p4.y * v1.x + p4.z * v2.x + p4.w * v3.x;
            u1 += p4.x * v0.y + p4.y * v1.y + p4.z * v2.y + p4.w * v3.y;
        }
        __syncthreads();
    }
    g_U[chunk][(bh * SLOTS + i) * DH + 2 * l]     = u0;
    g_U[chunk][(bh * SLOTS + i) * DH + 2 * l + 1] = u1;
#pragma unroll
    for (int o = 16; o; o >>= 1) zacc += __shfl_xor_sync(~0u, zacc, o);
    if (l == 0) g_Z[chunk][bh * SLOTS + i] = zacc;
}

// ---------------- iteration tail: Wc, GRU, LN, MLP + fused next-iter Q ----------
__global__ __launch_bounds__(256) void k_tail(const float* __restrict__ Wc,
                                              const float* __restrict__ Wih,
                                              const float* __restrict__ Whh,
                                              const float* __restrict__ bih,
                                              const float* __restrict__ bhh,
                                              const float* __restrict__ lnw,
                                              const float* __restrict__ lnb,
                                              const float* __restrict__ w1,
                                              const float* __restrict__ b1,
                                              const float* __restrict__ w2,
                                              const float* __restrict__ b2,
                                              const float* __restrict__ Wq,
                                              const float* __restrict__ lnsw,
                                              const float* __restrict__ lnsb,
                                              float* __restrict__ out, int write_out) {
    __shared__ float su[4][256];
    __shared__ float sc[4][256];
    __shared__ float sh[4][256];
    __shared__ float sgx[4][768];
    __shared__ float sgh[4][768];
    __shared__ float sm_[4][256];
    __shared__ float st1[4][128];
    __shared__ float smu[4], srs[4];
    const int tid = threadIdx.x;
    const int row0 = blockIdx.x * 4;

    for (int idx = tid; idx < 1024; idx += 256) {
        int r = idx >> 8, j = idx & 255;
        int grow = row0 + r;
        int b = grow >> 3, s = grow & 7;
        int h = j >> 6, dh = j & 63;
        int uo = ((b * HEADS + h) * SLOTS + s) * DH + dh;
        int zo = (b * HEADS + h) * SLOTS + s;
        float uu = 0.f, zz = 0.f;
#pragma unroll
        for (int cc = 0; cc < SPLIT; cc++) {
            uu += g_U[cc][uo];
            zz += g_Z[cc][zo];
        }
        su[r][j] = uu / zz;
        sh[r][j] = g_slots[grow * DIM + j];
    }
    __syncthreads();

    {
        float a0 = 0, a1 = 0, a2 = 0, a3 = 0;
        for (int i2 = 0; i2 < 256; i2++) {
            float w = Wc[i2 * 256 + tid];
            a0 += su[0][i2] * w; a1 += su[1][i2] * w;
            a2 += su[2][i2] * w; a3 += su[3][i2] * w;
        }
        sc[0][tid] = a0; sc[1][tid] = a1; sc[2][tid] = a2; sc[3][tid] = a3;
    }
    __syncthreads();

    {
        int w = tid >> 5, l = tid & 31;
        for (int r = w; r < 768; r += 8) {
            float ax0 = 0, ax1 = 0, ax2 = 0, ax3 = 0;
            float ah0 = 0, ah1 = 0, ah2 = 0, ah3 = 0;
            const float* wi = &Wih[r * 256];
            const float* wh = &Whh[r * 256];
#pragma unroll
            for (int t = 0; t < 8; t++) {
                int ii = l + 32 * t;
                float wiv = wi[ii], whv = wh[ii];
                ax0 += sc[0][ii] * wiv; ah0 += sh[0][ii] * whv;
                ax1 += sc[1][ii] * wiv; ah1 += sh[1][ii] * whv;
                ax2 += sc[2][ii] * wiv; ah2 += sh[2][ii] * whv;
                ax3 += sc[3][ii] * wiv; ah3 += sh[3][ii] * whv;
            }
#pragma unroll
            for (int o = 16; o; o >>= 1) {
                ax0 += __shfl_xor_sync(~0u, ax0, o); ax1 += __shfl_xor_sync(~0u, ax1, o);
                ax2 += __shfl_xor_sync(~0u, ax2, o); ax3 += __shfl_xor_sync(~0u, ax3, o);
                ah0 += __shfl_xor_sync(~0u, ah0, o); ah1 += __shfl_xor_sync(~0u, ah1, o);
                ah2 += __shfl_xor_sync(~0u, ah2, o); ah3 += __shfl_xor_sync(~0u, ah3, o);
            }
            if (l == 0) {
                float bi = bih[r], bh2 = bhh[r];
                sgx[0][r] = ax0 + bi; sgx[1][r] = ax1 + bi;
                sgx[2][r] = ax2 + bi; sgx[3][r] = ax3 + bi;
                sgh[0][r] = ah0 + bh2; sgh[1][r] = ah1 + bh2;
                sgh[2][r] = ah2 + bh2; sgh[3][r] = ah3 + bh2;
            }
        }
    }
    __syncthreads();

    {
        int d = tid;
#pragma unroll
        for (int r = 0; r < 4; r++) {
            float rr = 1.f / (1.f + __expf(-(sgx[r][d] + sgh[r][d])));
            float zz = 1.f / (1.f + __expf(-(sgx[r][256 + d] + sgh[r][256 + d])));
            float nn = tanhf(sgx[r][512 + d] + rr * sgh[r][512 + d]);
            su[r][d] = (1.f - zz) * nn + zz * sh[r][d];
        }
    }
    __syncthreads();

    {
        int w = tid >> 5, l = tid & 31;
        if (w < 4) {
            float s1 = 0.f;
#pragma unroll
            for (int t = 0; t < 8; t++) s1 += su[w][l + 32 * t];
#pragma unroll
            for (int o = 16; o; o >>= 1) s1 += __shfl_xor_sync(~0u, s1, o);
            float mean = s1 * (1.0f / 256.0f);
            float s2 = 0.f;
#pragma unroll
            for (int t = 0; t < 8; t++) {
                float dd = su[w][l + 32 * t] - mean;
                s2 += dd * dd;
            }
#pragma unroll
            for (int o = 16; o; o >>= 1) s2 += __shfl_xor_sync(~0u, s2, o);
            if (l == 0) { smu[w] = mean; srs[w] = rsqrtf(s2 * (1.0f / 256.0f) + 1e-5f); }
        }
    }
    __syncthreads();
    {
        int d = tid;
        float lw = lnw[d], lb = lnb[d];
#pragma unroll
        for (int r = 0; r < 4; r++)
            sm_[r][d] = (su[r][d] - smu[r]) * srs[r] * lw + lb;
    }
    __syncthreads();

    {
        int k = tid & 127;
        int rbase = (tid >> 7) * 2;
        float a0 = 0, a1 = 0;
        for (int d2 = 0; d2 < 256; d2++) {
            float w = w1[d2 * 128 + k];
            a0 += sm_[rbase][d2] * w;
            a1 += sm_[rbase + 1][d2] * w;
        }
        float bb1 = b1[k];
        st1[rbase][k]     = fmaxf(a0 + bb1, 0.f);
        st1[rbase + 1][k] = fmaxf(a1 + bb1, 0.f);
    }
    __syncthreads();

    {
        int d = tid;
        float a0 = 0, a1 = 0, a2 = 0, a3 = 0;
        for (int k2 = 0; k2 < 128; k2++) {
            float w = w2[k2 * 256 + d];
            a0 += st1[0][k2] * w; a1 += st1[1][k2] * w;
            a2 += st1[2][k2] * w; a3 += st1[3][k2] * w;
        }
        float bb2 = b2[d];
        float o0 = su[0][d] + a0 + bb2, o1 = su[1][d] + a1 + bb2;
        float o2 = su[2][d] + a2 + bb2, o3 = su[3][d] + a3 + bb2;
        g_slots[(row0 + 0) * DIM + d] = o0;
        g_slots[(row0 + 1) * DIM + d] = o1;
        g_slots[(row0 + 2) * DIM + d] = o2;
        g_slots[(row0 + 3) * DIM + d] = o3;
        if (write_out) {
            out[(row0 + 0) * DIM + d] = o0;
            out[(row0 + 1) * DIM + d] = o1;
            out[(row0 + 2) * DIM + d] = o2;
            out[(row0 + 3) * DIM + d] = o3;
        } else {
            // stage new slots for fused q projection
            sm_[0][d] = o0; sm_[1][d] = o1; sm_[2][d] = o2; sm_[3][d] = o3;
        }
    }

    // ---- fused next-iteration slot LN + Q projection (skip on last iter) ----
    if (!write_out) {
        __syncthreads();
        {
            int w = tid >> 5, l = tid & 31;
            if (w < 4) {
                float s1 = 0.f;
#pragma unroll
                for (int t = 0; t < 8; t++) s1 += sm_[w][l + 32 * t];
#pragma unroll
                for (int o = 16; o; o >>= 1) s1 += __shfl_xor_sync(~0u, s1, o);
                float mean = s1 * (1.0f / 256.0f);
                float s2 = 0.f;
#pragma unroll
                for (int t = 0; t < 8; t++) {
                    float dd = sm_[w][l + 32 * t] - mean;
                    s2 += dd * dd;
                }
#pragma unroll
                for (int o = 16; o; o >>= 1) s2 += __shfl_xor_sync(~0u, s2, o);
                if (l == 0) { smu[w] = mean; srs[w] = rsqrtf(s2 * (1.0f / 256.0f) + 1e-5f); }
            }
        }
        __syncthreads();
        {
            int d = tid;
            float lw = lnsw[d], lb = lnsb[d];
#pragma unroll
            for (int r = 0; r < 4; r++)
                su[r][d] = (sm_[r][d] - smu[r]) * srs[r] * lw + lb;
        }
        __syncthreads();
        {
            int j = tid;
            float a0 = 0, a1 = 0, a2 = 0, a3 = 0;
            for (int i2 = 0; i2 < 256; i2++) {
                float w = Wq[i2 * 256 + j];
                a0 += su[0][i2] * w; a1 += su[1][i2] * w;
                a2 += su[2][i2] * w; a3 += su[3][i2] * w;
            }
            int h = j >> 6, dh = j & 63;
            float av[4] = {a0, a1, a2, a3};
#pragma unroll
            for (int r = 0; r < 4; r++) {
                int grow = row0 + r;
                int b = grow >> 3, s = grow & 7;
                g_q[(((b * HEADS + h) * SLOTS) + s) * DH + dh] = av[r];
            }
        }
    }
}

// ---------------- launch ----------------
extern "C" void kernel_launch(void* const* d_in, const int* in_sizes, int n_in,
                              void* d_out, int out_size) {
    const float* inputs  = (const float*)d_in[0];
    const float* mu      = (const float*)d_in[1];
    const float* lsig    = (const float*)d_in[2];
    const float* ln_in_w = (const float*)d_in[3];
    const float* ln_in_b = (const float*)d_in[4];
    const float* ln_s_w  = (const float*)d_in[5];
    const float* ln_s_b  = (const float*)d_in[6];
    const float* Wq      = (const float*)d_in[7];
    const float* Wk      = (const float*)d_in[8];
    const float* Wv      = (const float*)d_in[9];
    const float* Wc      = (const float*)d_in[10];
    const float* Wih     = (const float*)d_in[11];
    const float* Whh     = (const float*)d_in[12];
    const float* bih     = (const float*)d_in[13];
    const float* bhh     = (const float*)d_in[14];
    const float* lnmw    = (const float*)d_in[15];
    const float* lnmb    = (const float*)d_in[16];
    const float* w1      = (const float*)d_in[17];
    const float* b1      = (const float*)d_in[18];
    const float* w2      = (const float*)d_in[19];
    const float* b2      = (const float*)d_in[20];
    float* out = (float*)d_out;

    cudaFuncSetAttribute(k_gemm_kv_mma, cudaFuncAttributeMaxDynamicSharedMemorySize, SM_TOTAL);

    k_init_slots<<<256, 256>>>(mu, lsig);
    k_prep_w<<<512, 256>>>(Wk, Wv);
    k_ln_in<<<BATCH * NTOK / 8, 256>>>(inputs, ln_in_w, ln_in_b);
    k_gemm_kv_mma<<<dim3(BATCH * NTOK / 128, 4), 256, SM_TOTAL>>>();

    k_slot_q<<<BATCH * SLOTS, 256>>>(Wq, ln_s_w, ln_s_b);
    for (int it = 0; it < ITERS; it++) {
        k_attn<<<dim3(SPLIT, HEADS, BATCH), 256>>>();
        k_tail<<<BATCH * SLOTS / 4, 256>>>(Wc, Wih, Whh, bih, bhh,
                                           lnmw, lnmb, w1, b1, w2, b2,
                                           Wq, ln_s_w, ln_s_b,
                                           out, it == ITERS - 1 ? 1 : 0);
    }
}

// round 15
// speedup vs baseline: 1.1251x; 1.1251x over previous
#include <cuda_runtime.h>
#include <cuda_bf16.h>
#include <cstdint>

#define BATCH 32
#define NTOK  4096
#define DIM   256
#define HEADS 4
#define DH    64
#define SLOTS 8
#define ITERS 3
#define SPLIT 8   // token chunks per (b,h) in attention

// ---------------- scratch (static device memory; no allocations) ----------------
__device__ float g_xln[BATCH * NTOK * DIM];             // LayerNorm'd inputs
__device__ __nv_bfloat16 g_k[BATCH * HEADS * NTOK * DH]; // (b,h,n,dh) bf16
__device__ __nv_bfloat16 g_v[BATCH * HEADS * NTOK * DH]; // (b,h,n,dh) bf16
__device__ float g_q[BATCH * HEADS * SLOTS * DH];       // (b,h,s,dh)
__device__ float g_slots[BATCH * SLOTS * DIM];          // current slots
__device__ float g_U[SPLIT][BATCH * HEADS * SLOTS * DH];// partial weighted V sums
__device__ float g_Z[SPLIT][BATCH * HEADS * SLOTS];     // partial attn mass
// transposed bf16 hi/lo weights: [kv][n (256)][k (256)]
__device__ __nv_bfloat16 g_bhi[2 * 256 * 256];
__device__ __nv_bfloat16 g_blo[2 * 256 * 256];

// ---------------- mma.sync helpers (base sm_103 PTX, no "a" features) ----------
__device__ __forceinline__ uint32_t smem_to_u32(const void* p) {
    uint32_t a;
    asm("{ .reg .u64 t; cvta.to.shared.u64 t, %1; cvt.u32.u64 %0, t; }" : "=r"(a) : "l"(p));
    return a;
}
__device__ __forceinline__ void ldsm_x4(uint32_t* r, uint32_t addr) {
    asm volatile("ldmatrix.sync.aligned.m8n8.x4.shared.b16 {%0,%1,%2,%3}, [%4];"
        : "=r"(r[0]), "=r"(r[1]), "=r"(r[2]), "=r"(r[3]) : "r"(addr));
}
__device__ __forceinline__ void ldsm_x2(uint32_t* r, uint32_t addr) {
    asm volatile("ldmatrix.sync.aligned.m8n8.x2.shared.b16 {%0,%1}, [%2];"
        : "=r"(r[0]), "=r"(r[1]) : "r"(addr));
}
__device__ __forceinline__ void mma16816(float* c, const uint32_t* a, const uint32_t* b) {
    asm volatile("mma.sync.aligned.m16n8k16.row.col.f32.bf16.bf16.f32 "
        "{%0,%1,%2,%3}, {%4,%5,%6,%7}, {%8,%9}, {%0,%1,%2,%3};"
        : "+f"(c[0]), "+f"(c[1]), "+f"(c[2]), "+f"(c[3])
        : "r"(a[0]), "r"(a[1]), "r"(a[2]), "r"(a[3]), "r"(b[0]), "r"(b[1]));
}
// XOR swizzle: rows of 128B, 16B chunks, chunk ^= (row & 7)
__device__ __forceinline__ uint32_t swz(uint32_t row, uint32_t kbyte) {
    return row * 128 + ((((kbyte >> 4) ^ (row & 7)) << 4) | (kbyte & 15));
}

// ---------------- slot init: Threefry2x32, JAX partitionable path, key(42) ------
__device__ __forceinline__ unsigned rotl32(unsigned x, int r) {
    return __funnelshift_l(x, x, r);
}

__global__ __launch_bounds__(256) void k_init_slots(const float* __restrict__ mu,
                                                    const float* __restrict__ lsig) {
    unsigned idx = blockIdx.x * blockDim.x + threadIdx.x;  // 0..65535
    if (idx >= 65536u) return;
    const unsigned K0 = 0u, K1 = 42u, K2 = 0x1BD11BDAu ^ 0u ^ 42u;
    unsigned x0 = 0u, x1 = idx;
    x0 += K0; x1 += K1;
#define TFR(r) { x0 += x1; x1 = rotl32(x1, r); x1 ^= x0; }
    TFR(13) TFR(15) TFR(26) TFR(6)
    x0 += K1; x1 += K2 + 1u;
    TFR(17) TFR(29) TFR(16) TFR(24)
    x0 += K2; x1 += K0 + 2u;
    TFR(13) TFR(15) TFR(26) TFR(6)
    x0 += K0; x1 += K1 + 3u;
    TFR(17) TFR(29) TFR(16) TFR(24)
    x0 += K1; x1 += K2 + 4u;
    TFR(13) TFR(15) TFR(26) TFR(6)
    x0 += K2; x1 += K0 + 5u;
#undef TFR
    unsigned bits = x0 ^ x1;
    const float LO = -0.99999994f;
    float f = __uint_as_float((bits >> 9) | 0x3F800000u) - 1.0f;
    float u = fmaxf(LO, f * 2.0f + LO);
    float nz = 1.41421356237309515f * erfinvf(u);
    int d = idx & 255;
    g_slots[idx] = mu[d] + expf(lsig[d]) * nz;
}

// ---------------- LayerNorm of inputs: one WARP per row, no block barriers ------
__global__ __launch_bounds__(256) void k_ln_in(const float* __restrict__ x,
                                               const float* __restrict__ w,
                                               const float* __restrict__ b) {
    const int wid = threadIdx.x >> 5, lane = threadIdx.x & 31;
    const int row = blockIdx.x * 8 + wid;
    const float* src = x + (size_t)row * DIM + lane * 8;
    float4 a0 = *reinterpret_cast<const float4*>(src);
    float4 a1 = *reinterpret_cast<const float4*>(src + 4);
    float s = a0.x + a0.y + a0.z + a0.w + a1.x + a1.y + a1.z + a1.w;
#pragma unroll
    for (int o = 16; o; o >>= 1) s += __shfl_xor_sync(~0u, s, o);
    float mean = s * (1.0f / 256.0f);
    float d0 = a0.x - mean, d1 = a0.y - mean, d2 = a0.z - mean, d3 = a0.w - mean;
    float d4 = a1.x - mean, d5 = a1.y - mean, d6 = a1.z - mean, d7 = a1.w - mean;
    float s2 = d0*d0 + d1*d1 + d2*d2 + d3*d3 + d4*d4 + d5*d5 + d6*d6 + d7*d7;
#pragma unroll
    for (int o = 16; o; o >>= 1) s2 += __shfl_xor_sync(~0u, s2, o);
    float rs = rsqrtf(s2 * (1.0f / 256.0f) + 1e-5f);
    const float4 w0 = *reinterpret_cast<const float4*>(w + lane * 8);
    const float4 w1 = *reinterpret_cast<const float4*>(w + lane * 8 + 4);
    const float4 b0 = *reinterpret_cast<const float4*>(b + lane * 8);
    const float4 b1 = *reinterpret_cast<const float4*>(b + lane * 8 + 4);
    float4 o0, o1;
    o0.x = d0 * rs * w0.x + b0.x; o0.y = d1 * rs * w0.y + b0.y;
    o0.z = d2 * rs * w0.z + b0.z; o0.w = d3 * rs * w0.w + b0.w;
    o1.x = d4 * rs * w1.x + b1.x; o1.y = d5 * rs * w1.y + b1.y;
    o1.z = d6 * rs * w1.z + b1.z; o1.w = d7 * rs * w1.w + b1.w;
    float* dst = g_xln + (size_t)row * DIM + lane * 8;
    *reinterpret_cast<float4*>(dst) = o0;
    *reinterpret_cast<float4*>(dst + 4) = o1;
}

// ---------------- weight prep: W^T -> bf16 hi/lo ----------------
__global__ __launch_bounds__(256) void k_prep_w(const float* __restrict__ Wk,
                                                const float* __restrict__ Wv) {
    int idx = blockIdx.x * 256 + threadIdx.x;   // 0..131071
    int kv = idx >> 16;
    int rest = idx & 65535;
    int n = rest >> 8, k = rest & 255;
    float w = (kv ? Wv : Wk)[k * 256 + n];
    __nv_bfloat16 h = __float2bfloat16(w);
    __nv_bfloat16 l = __float2bfloat16(w - __bfloat162float(h));
    g_bhi[idx] = h;
    g_blo[idx] = l;
}

// ---------------- K/V GEMM via mma.sync bf16 hi/lo split (R10 config) ----------
#define SM_AHI 0
#define SM_ALO 16384
#define SM_BHI 32768
#define SM_BLO 49152
#define SM_TOTAL 65536

__global__ __launch_bounds__(256) void k_gemm_kv_mma() {
    extern __shared__ __align__(128) char sm[];
    const int tid = threadIdx.x, wid = tid >> 5, lane = tid & 31;
    const int m0 = blockIdx.x * 128;
    const int nb = blockIdx.y;
    const int kv = nb >> 1;
    const int nloc0 = (nb & 1) * 128;
    const uint32_t smb = smem_to_u32(sm);

    const int wm = (wid >> 2) * 64;
    const int wn = (wid & 3) * 32;

    float acc[4][4][4];
#pragma unroll
    for (int i = 0; i < 4; i++)
#pragma unroll
        for (int j = 0; j < 4; j++)
#pragma unroll
            for (int t = 0; t < 4; t++) acc[i][j][t] = 0.f;

    const int ar = tid >> 1, ah = (tid & 1) * 32;
    const int brow = tid >> 1, bkh = (tid & 1) * 32;
    const float* asrc = &g_xln[(size_t)(m0 + ar) * 256 + ah];
    const __nv_bfloat16* bhsrc = &g_bhi[(size_t)(kv * 256 + nloc0 + brow) * 256 + bkh];
    const __nv_bfloat16* blsrc = &g_blo[(size_t)(kv * 256 + nloc0 + brow) * 256 + bkh];

    const int rowA = wm + (lane & 15);
    const int colAsel = (lane >> 4) * 8;
    const int rowB = wn + (lane & 7);
    const int colBsel = ((lane >> 3) & 1) * 8;

    for (int c = 0; c < 4; c++) {
#pragma unroll
        for (int i = 0; i < 8; i++) {
            float4 a = *reinterpret_cast<const float4*>(asrc + c * 64 + i * 4);
            __nv_bfloat162 h01 = __floats2bfloat162_rn(a.x, a.y);
            __nv_bfloat162 h23 = __floats2bfloat162_rn(a.z, a.w);
            float lx = a.x - __bfloat162float(h01.x);
            float ly = a.y - __bfloat162float(h01.y);
            float lz = a.z - __bfloat162float(h23.x);
            float lw = a.w - __bfloat162float(h23.y);
            __nv_bfloat162 l01 = __floats2bfloat162_rn(lx, ly);
            __nv_bfloat162 l23 = __floats2bfloat162_rn(lz, lw);
            uint32_t sw = swz(ar, (ah + i * 4) * 2);
            uint2 hv, lv;
            hv.x = *reinterpret_cast<uint32_t*>(&h01);
            hv.y = *reinterpret_cast<uint32_t*>(&h23);
            lv.x = *reinterpret_cast<uint32_t*>(&l01);
            lv.y = *reinterpret_cast<uint32_t*>(&l23);
            *reinterpret_cast<uint2*>(sm + SM_AHI + sw) = hv;
            *reinterpret_cast<uint2*>(sm + SM_ALO + sw) = lv;
        }
#pragma unroll
        for (int i = 0; i < 4; i++) {
            uint4 hv = *reinterpret_cast<const uint4*>(bhsrc + c * 64 + i * 8);
            uint4 lv = *reinterpret_cast<const uint4*>(blsrc + c * 64 + i * 8);
            uint32_t sw = swz(brow, (bkh + i * 8) * 2);
            *reinterpret_cast<uint4*>(sm + SM_BHI + sw) = hv;
            *reinterpret_cast<uint4*>(sm + SM_BLO + sw) = lv;
        }
        __syncthreads();

#pragma unroll
        for (int kk = 0; kk < 64; kk += 16) {
            uint32_t Af[4][4], Bh[4][2], Bl[4][2];
            const uint32_t colA2 = (kk + colAsel) * 2;
            const uint32_t colB2 = (kk + colBsel) * 2;
#pragma unroll
            for (int mf = 0; mf < 4; mf++)
                ldsm_x4(Af[mf], smb + SM_AHI + swz(rowA + mf * 16, colA2));
#pragma unroll
            for (int nf = 0; nf < 4; nf++)
                ldsm_x2(Bh[nf], smb + SM_BHI + swz(rowB + nf * 8, colB2));
#pragma unroll
            for (int mf = 0; mf < 4; mf++)
#pragma unroll
                for (int nf = 0; nf < 4; nf++)
                    mma16816(acc[mf][nf], Af[mf], Bh[nf]);
#pragma unroll
            for (int nf = 0; nf < 4; nf++)
                ldsm_x2(Bl[nf], smb + SM_BLO + swz(rowB + nf * 8, colB2));
#pragma unroll
            for (int mf = 0; mf < 4; mf++)
#pragma unroll
                for (int nf = 0; nf < 4; nf++)
                    mma16816(acc[mf][nf], Af[mf], Bl[nf]);
#pragma unroll
            for (int mf = 0; mf < 4; mf++)
                ldsm_x4(Af[mf], smb + SM_ALO + swz(rowA + mf * 16, colA2));
#pragma unroll
            for (int mf = 0; mf < 4; mf++)
#pragma unroll
                for (int nf = 0; nf < 4; nf++)
                    mma16816(acc[mf][nf], Af[mf], Bh[nf]);
        }
        __syncthreads();
    }

    const int g = lane >> 2, tg = lane & 3;
#pragma unroll
    for (int mf = 0; mf < 4; mf++) {
#pragma unroll
        for (int nf = 0; nf < 4; nf++) {
            int col = nb * 128 + wn + nf * 8 + tg * 2;
            __nv_bfloat16* buf = (col < 256) ? g_k : g_v;
            int c8 = col & 255;
            int h = c8 >> 6, dh = c8 & 63;
            int m = m0 + wm + mf * 16 + g;
            int b = m >> 12, n = m & 4095;
            __nv_bfloat16* dst = buf + (size_t)(((b * HEADS + h) * NTOK) + n) * DH + dh;
            __nv_bfloat162 lo = __floats2bfloat162_rn(acc[mf][nf][0], acc[mf][nf][1]);
            __nv_bfloat162 hi2 = __floats2bfloat162_rn(acc[mf][nf][2], acc[mf][nf][3]);
            *reinterpret_cast<uint32_t*>(dst) = *reinterpret_cast<uint32_t*>(&lo);
            *reinterpret_cast<uint32_t*>(dst + 8 * DH) = *reinterpret_cast<uint32_t*>(&hi2);
        }
    }
}

// ---------------- slot LN + Q projection (one block per (b,s)) ----------------
__global__ __launch_bounds__(256) void k_slot_q(const float* __restrict__ Wq,
                                                const float* __restrict__ w,
                                                const float* __restrict__ b) {
    int row = blockIdx.x;   // b*8 + s
    int j = threadIdx.x;
    __shared__ float sln[256];
    __shared__ float red[8];
    float v = g_slots[row * DIM + j];
    float s = v;
#pragma unroll
    for (int o = 16; o; o >>= 1) s += __shfl_xor_sync(~0u, s, o);
    if ((j & 31) == 0) red[j >> 5] = s;
    __syncthreads();
    float tot = 0.f;
#pragma unroll
    for (int t = 0; t < 8; t++) tot += red[t];
    float mean = tot * (1.0f / 256.0f);
    __syncthreads();
    float dv = v - mean;
    float s2 = dv * dv;
#pragma unroll
    for (int o = 16; o; o >>= 1) s2 += __shfl_xor_sync(~0u, s2, o);
    if ((j & 31) == 0) red[j >> 5] = s2;
    __syncthreads();
    float tv = 0.f;
#pragma unroll
    for (int t = 0; t < 8; t++) tv += red[t];
    sln[j] = dv * rsqrtf(tv * (1.0f / 256.0f) + 1e-5f) * w[j] + b[j];
    __syncthreads();
    float acc = 0.f;
    for (int i = 0; i < 256; i++) acc += sln[i] * Wq[i * 256 + j];
    int bb = row >> 3, sl = row & 7, h = j >> 6, dh = j & 63;
    g_q[(((bb * HEADS + h) * SLOTS) + sl) * DH + dh] = acc;
}

// ---------------- fused attention: bf16 K/V, 64-token tiles (R13 version) -------
__global__ __launch_bounds__(256) void k_attn() {
    const int chunk = blockIdx.x, h = blockIdx.y, b = blockIdx.z;
    const int tid = threadIdx.x;
    const int i = tid >> 5;   // slot (warp)
    const int l = tid & 31;   // lane
    const int bh = b * HEADS + h;

    __shared__ float q[8][64];
    __shared__ float kT[64][65];
    __shared__ __align__(16) float vb[64][64];
    __shared__ float dt[64][9];
    __shared__ float pt[64][9];

    for (int idx = tid; idx < 512; idx += 256)
        q[idx >> 6][idx & 63] = g_q[bh * 512 + idx];

    const __nv_bfloat16* kbase = &g_k[(size_t)bh * NTOK * DH];
    const __nv_bfloat16* vbase = &g_v[(size_t)bh * NTOK * DH];
    const int TOK = NTOK / SPLIT;   // 512
    const int NT = TOK / 64;        // 8
    const int j0base = chunk * TOK;

    float u0 = 0.f, u1 = 0.f, zacc = 0.f;

    uint4 kr[2], vr[2];
#pragma unroll
    for (int qq = 0; qq < 2; qq++) {
        int id = tid + qq * 256;
        int t = id >> 3, d8 = (id & 7) * 8;
        kr[qq] = *reinterpret_cast<const uint4*>(kbase + (size_t)(j0base + t) * DH + d8);
        vr[qq] = *reinterpret_cast<const uint4*>(vbase + (size_t)(j0base + t) * DH + d8);
    }
    __syncthreads();   // q ready

    for (int tile = 0; tile < NT; tile++) {
#pragma unroll
        for (int qq = 0; qq < 2; qq++) {
            int id = tid + qq * 256;
            int t = id >> 3, d8 = (id & 7) * 8;
            const __nv_bfloat162* kp = reinterpret_cast<const __nv_bfloat162*>(&kr[qq]);
            const __nv_bfloat162* vp = reinterpret_cast<const __nv_bfloat162*>(&vr[qq]);
#pragma unroll
            for (int e = 0; e < 4; e++) {
                float2 kf = __bfloat1622float2(kp[e]);
                kT[d8 + 2 * e][t]     = kf.x;
                kT[d8 + 2 * e + 1][t] = kf.y;
            }
            float2 f0 = __bfloat1622float2(vp[0]);
            float2 f1 = __bfloat1622float2(vp[1]);
            float2 f2 = __bfloat1622float2(vp[2]);
            float2 f3 = __bfloat1622float2(vp[3]);
            float4 v04 = {f0.x, f0.y, f1.x, f1.y};
            float4 v14 = {f2.x, f2.y, f3.x, f3.y};
            *reinterpret_cast<float4*>(&vb[t][d8])     = v04;
            *reinterpret_cast<float4*>(&vb[t][d8 + 4]) = v14;
        }
        __syncthreads();

        if (tile + 1 < NT) {
            const int j0n = j0base + (tile + 1) * 64;
#pragma unroll
            for (int qq = 0; qq < 2; qq++) {
                int id = tid + qq * 256;
                int t = id >> 3, d8 = (id & 7) * 8;
                kr[qq] = *reinterpret_cast<const uint4*>(kbase + (size_t)(j0n + t) * DH + d8);
                vr[qq] = *reinterpret_cast<const uint4*>(vbase + (size_t)(j0n + t) * DH + d8);
            }
        }

        float a0 = 0.f, a1 = 0.f;
#pragma unroll 8
        for (int d = 0; d < 64; d++) {
            float qv = q[i][d];
            a0 += qv * kT[d][l];
            a1 += qv * kT[d][l + 32];
        }
        dt[l][i]      = a0 * 0.125f;
        dt[l + 32][i] = a1 * 0.125f;
        __syncthreads();

#pragma unroll
        for (int half = 0; half < 2; half++) {
            int t = l + half * 32;
            float mx = dt[t][0];
#pragma unroll
            for (int jj = 1; jj < 8; jj++) mx = fmaxf(mx, dt[t][jj]);
            float ss = 0.f;
#pragma unroll
            for (int jj = 0; jj < 8; jj++) ss += __expf(dt[t][jj] - mx);
            float p = __expf(dt[t][i] - mx) / ss + 1e-8f;
            zacc += p;
            pt[t][i] = p;
        }
        __syncthreads();

#pragma unroll 8
        for (int t = 0; t < 64; t++) {
            float pv = pt[t][i];
            float2 v2 = *reinterpret_cast<const float2*>(&vb[t][2 * l]);
            u0 += pv * v2.x;
            u1 += pv * v2.y;
        }
        __syncthreads();
    }
    g_U[chunk][(bh * SLOTS + i) * DH + 2 * l]     = u0;
    g_U[chunk][(bh * SLOTS + i) * DH + 2 * l + 1] = u1;
#pragma unroll
    for (int o = 16; o; o >>= 1) zacc += __shfl_xor_sync(~0u, zacc, o);
    if (l == 0) g_Z[chunk][bh * SLOTS + i] = zacc;
}

// ---------------- iteration tail: Wc, GRU, LN, MLP (2 rows per block) -----------
__global__ __launch_bounds__(256) void k_tail(const float* __restrict__ Wc,
                                              const float* __restrict__ Wih,
                                              const float* __restrict__ Whh,
                                              const float* __restrict__ bih,
                                              const float* __restrict__ bhh,
                                              const float* __restrict__ lnw,
                                              const float* __restrict__ lnb,
                                              const float* __restrict__ w1,
                                              const float* __restrict__ b1,
                                              const float* __restrict__ w2,
                                              const float* __restrict__ b2,
                                              float* __restrict__ out, int write_out) {
    __shared__ float su[2][256];
    __shared__ float sc[2][256];
    __shared__ float sh[2][256];
    __shared__ float sgx[2][768];
    __shared__ float sgh[2][768];
    __shared__ float sm_[2][256];
    __shared__ float st1[2][128];
    __shared__ float smu[2], srs[2];
    const int tid = threadIdx.x;
    const int row0 = blockIdx.x * 2;

    // Phase A: updates = U/Z + slots_prev
    for (int idx = tid; idx < 512; idx += 256) {
        int r = idx >> 8, j = idx & 255;
        int grow = row0 + r;
        int b = grow >> 3, s = grow & 7;
        int h = j >> 6, dh = j & 63;
        int uo = ((b * HEADS + h) * SLOTS + s) * DH + dh;
        int zo = (b * HEADS + h) * SLOTS + s;
        float uu = 0.f, zz = 0.f;
#pragma unroll
        for (int cc = 0; cc < SPLIT; cc++) {
            uu += g_U[cc][uo];
            zz += g_Z[cc][zo];
        }
        su[r][j] = uu / zz;
        sh[r][j] = g_slots[grow * DIM + j];
    }
    __syncthreads();

    // Phase B: c = updates @ Wc
    {
        float a0 = 0, a1 = 0;
        for (int i2 = 0; i2 < 256; i2++) {
            float w = Wc[i2 * 256 + tid];
            a0 += su[0][i2] * w;
            a1 += su[1][i2] * w;
        }
        sc[0][tid] = a0; sc[1][tid] = a1;
    }
    __syncthreads();

    // Phase C: gx = c @ Wih^T + bih ; gh = h @ Whh^T + bhh
    {
        int w = tid >> 5, l = tid & 31;
        for (int r = w; r < 768; r += 8) {
            float ax0 = 0, ax1 = 0, ah0 = 0, ah1 = 0;
            const float* wi = &Wih[r * 256];
            const float* wh = &Whh[r * 256];
#pragma unroll
            for (int t = 0; t < 8; t++) {
                int ii = l + 32 * t;
                float wiv = wi[ii], whv = wh[ii];
                ax0 += sc[0][ii] * wiv; ah0 += sh[0][ii] * whv;
                ax1 += sc[1][ii] * wiv; ah1 += sh[1][ii] * whv;
            }
#pragma unroll
            for (int o = 16; o; o >>= 1) {
                ax0 += __shfl_xor_sync(~0u, ax0, o); ax1 += __shfl_xor_sync(~0u, ax1, o);
                ah0 += __shfl_xor_sync(~0u, ah0, o); ah1 += __shfl_xor_sync(~0u, ah1, o);
            }
            if (l == 0) {
                float bi = bih[r], bh2 = bhh[r];
                sgx[0][r] = ax0 + bi; sgx[1][r] = ax1 + bi;
                sgh[0][r] = ah0 + bh2; sgh[1][r] = ah1 + bh2;
            }
        }
    }
    __syncthreads();

    // Phase D: GRU gates (r,z,n) -> pre (into su)
    {
        int d = tid;
#pragma unroll
        for (int r = 0; r < 2; r++) {
            float rr = 1.f / (1.f + __expf(-(sgx[r][d] + sgh[r][d])));
            float zz = 1.f / (1.f + __expf(-(sgx[r][256 + d] + sgh[r][256 + d])));
            float nn = tanhf(sgx[r][512 + d] + rr * sgh[r][512 + d]);
            su[r][d] = (1.f - zz) * nn + zz * sh[r][d];
        }
    }
    __syncthreads();

    // LN per row (warps 0..1)
    {
        int w = tid >> 5, l = tid & 31;
        if (w < 2) {
            float s1 = 0.f;
#pragma unroll
            for (int t = 0; t < 8; t++) s1 += su[w][l + 32 * t];
#pragma unroll
            for (int o = 16; o; o >>= 1) s1 += __shfl_xor_sync(~0u, s1, o);
            float mean = s1 * (1.0f / 256.0f);
            float s2 = 0.f;
#pragma unroll
            for (int t = 0; t < 8; t++) {
                float dd = su[w][l + 32 * t] - mean;
                s2 += dd * dd;
            }
#pragma unroll
            for (int o = 16; o; o >>= 1) s2 += __shfl_xor_sync(~0u, s2, o);
            if (l == 0) { smu[w] = mean; srs[w] = rsqrtf(s2 * (1.0f / 256.0f) + 1e-5f); }
        }
    }
    __syncthreads();
    {
        int d = tid;
        float lw = lnw[d], lb = lnb[d];
#pragma unroll
        for (int r = 0; r < 2; r++)
            sm_[r][d] = (su[r][d] - smu[r]) * srs[r] * lw + lb;
    }
    __syncthreads();

    // Phase E: t1 = relu(m @ w1 + b1)  (thread -> (row = tid>>7, k = tid&127))
    {
        int k = tid & 127;
        int r = tid >> 7;
        float a0 = 0;
        for (int d2 = 0; d2 < 256; d2++)
            a0 += sm_[r][d2] * w1[d2 * 128 + k];
        st1[r][k] = fmaxf(a0 + b1[k], 0.f);
    }
    __syncthreads();

    // Phase F: out = pre + t1 @ w2 + b2
    {
        int d = tid;
        float a0 = 0, a1 = 0;
        for (int k2 = 0; k2 < 128; k2++) {
            float w = w2[k2 * 256 + d];
            a0 += st1[0][k2] * w;
            a1 += st1[1][k2] * w;
        }
        float bb2 = b2[d];
        float o0 = su[0][d] + a0 + bb2, o1 = su[1][d] + a1 + bb2;
        g_slots[(row0 + 0) * DIM + d] = o0;
        g_slots[(row0 + 1) * DIM + d] = o1;
        if (write_out) {
            out[(row0 + 0) * DIM + d] = o0;
            out[(row0 + 1) * DIM + d] = o1;
        }
    }
}

// ---------------- launch ----------------
extern "C" void kernel_launch(void* const* d_in, const int* in_sizes, int n_in,
                              void* d_out, int out_size) {
    const float* inputs  = (const float*)d_in[0];
    const float* mu      = (const float*)d_in[1];
    const float* lsig    = (const float*)d_in[2];
    const float* ln_in_w = (const float*)d_in[3];
    const float* ln_in_b = (const float*)d_in[4];
    const float* ln_s_w  = (const float*)d_in[5];
    const float* ln_s_b  = (const float*)d_in[6];
    const float* Wq      = (const float*)d_in[7];
    const float* Wk      = (const float*)d_in[8];
    const float* Wv      = (const float*)d_in[9];
    const float* Wc      = (const float*)d_in[10];
    const float* Wih     = (const float*)d_in[11];
    const float* Whh     = (const float*)d_in[12];
    const float* bih     = (const float*)d_in[13];
    const float* bhh     = (const float*)d_in[14];
    const float* lnmw    = (const float*)d_in[15];
    const float* lnmb    = (const float*)d_in[16];
    const float* w1      = (const float*)d_in[17];
    const float* b1      = (const float*)d_in[18];
    const float* w2      = (const float*)d_in[19];
    const float* b2      = (const float*)d_in[20];
    float* out = (float*)d_out;

    cudaFuncSetAttribute(k_gemm_kv_mma, cudaFuncAttributeMaxDynamicSharedMemorySize, SM_TOTAL);

    k_init_slots<<<256, 256>>>(mu, lsig);
    k_prep_w<<<512, 256>>>(Wk, Wv);
    k_ln_in<<<BATCH * NTOK / 8, 256>>>(inputs, ln_in_w, ln_in_b);
    k_gemm_kv_mma<<<dim3(BATCH * NTOK / 128, 4), 256, SM_TOTAL>>>();

    for (int it = 0; it < ITERS; it++) {
        k_slot_q<<<BATCH * SLOTS, 256>>>(Wq, ln_s_w, ln_s_b);
        k_attn<<<dim3(SPLIT, HEADS, BATCH), 256>>>();
        k_tail<<<BATCH * SLOTS / 2, 256>>>(Wc, Wih, Whh, bih, bhh,
                                           lnmw, lnmb, w1, b1, w2, b2,
                                           out, it == ITERS - 1 ? 1 : 0);
    }
}

// round 16
// speedup vs baseline: 1.3732x; 1.2205x over previous
#include <cuda_runtime.h>
#include <cuda_bf16.h>
#include <cstdint>

#define BATCH 32
#define NTOK  4096
#define DIM   256
#define HEADS 4
#define DH    64
#define SLOTS 8
#define ITERS 3
#define SPLIT 8   // token chunks per (b,h) in attention

// ---------------- scratch (static device memory; no allocations) ----------------
__device__ float g_xln[BATCH * NTOK * DIM];             // LayerNorm'd inputs
__device__ __nv_bfloat16 g_k[BATCH * HEADS * NTOK * DH]; // (b,h,n,dh) bf16
__device__ __nv_bfloat16 g_v[BATCH * HEADS * NTOK * DH]; // (b,h,n,dh) bf16
__device__ float g_q[BATCH * HEADS * SLOTS * DH];       // (b,h,s,dh)
__device__ float g_slots[BATCH * SLOTS * DIM];          // current slots
__device__ float g_U[SPLIT][BATCH * HEADS * SLOTS * DH];// partial weighted V sums
__device__ float g_Z[SPLIT][BATCH * HEADS * SLOTS];     // partial attn mass
// transposed bf16 hi/lo weights: [kv][n (256)][k (256)]
__device__ __nv_bfloat16 g_bhi[2 * 256 * 256];
__device__ __nv_bfloat16 g_blo[2 * 256 * 256];

// ---------------- mma.sync helpers (base sm_103 PTX, no "a" features) ----------
__device__ __forceinline__ uint32_t smem_to_u32(const void* p) {
    uint32_t a;
    asm("{ .reg .u64 t; cvta.to.shared.u64 t, %1; cvt.u32.u64 %0, t; }" : "=r"(a) : "l"(p));
    return a;
}
__device__ __forceinline__ void ldsm_x4(uint32_t* r, uint32_t addr) {
    asm volatile("ldmatrix.sync.aligned.m8n8.x4.shared.b16 {%0,%1,%2,%3}, [%4];"
        : "=r"(r[0]), "=r"(r[1]), "=r"(r[2]), "=r"(r[3]) : "r"(addr));
}
// non-trans: smem [n][k] (k contiguous) -> m16n8k16 B fragment
__device__ __forceinline__ void ldsm_x2(uint32_t* r, uint32_t addr) {
    asm volatile("ldmatrix.sync.aligned.m8n8.x2.shared.b16 {%0,%1}, [%2];"
        : "=r"(r[0]), "=r"(r[1]) : "r"(addr));
}
// trans: smem [k][n] (n contiguous) -> m16n8k16 B fragment (flash-attn V path)
__device__ __forceinline__ void ldsm_x2_t(uint32_t* r, uint32_t addr) {
    asm volatile("ldmatrix.sync.aligned.m8n8.x2.trans.shared.b16 {%0,%1}, [%2];"
        : "=r"(r[0]), "=r"(r[1]) : "r"(addr));
}
__device__ __forceinline__ void mma16816(float* c, const uint32_t* a, const uint32_t* b) {
    asm volatile("mma.sync.aligned.m16n8k16.row.col.f32.bf16.bf16.f32 "
        "{%0,%1,%2,%3}, {%4,%5,%6,%7}, {%8,%9}, {%0,%1,%2,%3};"
        : "+f"(c[0]), "+f"(c[1]), "+f"(c[2]), "+f"(c[3])
        : "r"(a[0]), "r"(a[1]), "r"(a[2]), "r"(a[3]), "r"(b[0]), "r"(b[1]));
}
// XOR swizzle: rows of 128B, 16B chunks, chunk ^= (row & 7)
__device__ __forceinline__ uint32_t swz(uint32_t row, uint32_t kbyte) {
    return row * 128 + ((((kbyte >> 4) ^ (row & 7)) << 4) | (kbyte & 15));
}

// ---------------- slot init: Threefry2x32, JAX partitionable path, key(42) ------
__device__ __forceinline__ unsigned rotl32(unsigned x, int r) {
    return __funnelshift_l(x, x, r);
}

__global__ __launch_bounds__(256) void k_init_slots(const float* __restrict__ mu,
                                                    const float* __restrict__ lsig) {
    unsigned idx = blockIdx.x * blockDim.x + threadIdx.x;  // 0..65535
    if (idx >= 65536u) return;
    const unsigned K0 = 0u, K1 = 42u, K2 = 0x1BD11BDAu ^ 0u ^ 42u;
    unsigned x0 = 0u, x1 = idx;
    x0 += K0; x1 += K1;
#define TFR(r) { x0 += x1; x1 = rotl32(x1, r); x1 ^= x0; }
    TFR(13) TFR(15) TFR(26) TFR(6)
    x0 += K1; x1 += K2 + 1u;
    TFR(17) TFR(29) TFR(16) TFR(24)
    x0 += K2; x1 += K0 + 2u;
    TFR(13) TFR(15) TFR(26) TFR(6)
    x0 += K0; x1 += K1 + 3u;
    TFR(17) TFR(29) TFR(16) TFR(24)
    x0 += K1; x1 += K2 + 4u;
    TFR(13) TFR(15) TFR(26) TFR(6)
    x0 += K2; x1 += K0 + 5u;
#undef TFR
    unsigned bits = x0 ^ x1;
    const float LO = -0.99999994f;
    float f = __uint_as_float((bits >> 9) | 0x3F800000u) - 1.0f;
    float u = fmaxf(LO, f * 2.0f + LO);
    float nz = 1.41421356237309515f * erfinvf(u);
    int d = idx & 255;
    g_slots[idx] = mu[d] + expf(lsig[d]) * nz;
}

// ---------------- LayerNorm of inputs: one WARP per row, no block barriers ------
__global__ __launch_bounds__(256) void k_ln_in(const float* __restrict__ x,
                                               const float* __restrict__ w,
                                               const float* __restrict__ b) {
    const int wid = threadIdx.x >> 5, lane = threadIdx.x & 31;
    const int row = blockIdx.x * 8 + wid;
    const float* src = x + (size_t)row * DIM + lane * 8;
    float4 a0 = *reinterpret_cast<const float4*>(src);
    float4 a1 = *reinterpret_cast<const float4*>(src + 4);
    float s = a0.x + a0.y + a0.z + a0.w + a1.x + a1.y + a1.z + a1.w;
#pragma unroll
    for (int o = 16; o; o >>= 1) s += __shfl_xor_sync(~0u, s, o);
    float mean = s * (1.0f / 256.0f);
    float d0 = a0.x - mean, d1 = a0.y - mean, d2 = a0.z - mean, d3 = a0.w - mean;
    float d4 = a1.x - mean, d5 = a1.y - mean, d6 = a1.z - mean, d7 = a1.w - mean;
    float s2 = d0*d0 + d1*d1 + d2*d2 + d3*d3 + d4*d4 + d5*d5 + d6*d6 + d7*d7;
#pragma unroll
    for (int o = 16; o; o >>= 1) s2 += __shfl_xor_sync(~0u, s2, o);
    float rs = rsqrtf(s2 * (1.0f / 256.0f) + 1e-5f);
    const float4 w0 = *reinterpret_cast<const float4*>(w + lane * 8);
    const float4 w1 = *reinterpret_cast<const float4*>(w + lane * 8 + 4);
    const float4 b0 = *reinterpret_cast<const float4*>(b + lane * 8);
    const float4 b1 = *reinterpret_cast<const float4*>(b + lane * 8 + 4);
    float4 o0, o1;
    o0.x = d0 * rs * w0.x + b0.x; o0.y = d1 * rs * w0.y + b0.y;
    o0.z = d2 * rs * w0.z + b0.z; o0.w = d3 * rs * w0.w + b0.w;
    o1.x = d4 * rs * w1.x + b1.x; o1.y = d5 * rs * w1.y + b1.y;
    o1.z = d6 * rs * w1.z + b1.z; o1.w = d7 * rs * w1.w + b1.w;
    float* dst = g_xln + (size_t)row * DIM + lane * 8;
    *reinterpret_cast<float4*>(dst) = o0;
    *reinterpret_cast<float4*>(dst + 4) = o1;
}

// ---------------- weight prep: W^T -> bf16 hi/lo ----------------
__global__ __launch_bounds__(256) void k_prep_w(const float* __restrict__ Wk,
                                                const float* __restrict__ Wv) {
    int idx = blockIdx.x * 256 + threadIdx.x;   // 0..131071
    int kv = idx >> 16;
    int rest = idx & 65535;
    int n = rest >> 8, k = rest & 255;
    float w = (kv ? Wv : Wk)[k * 256 + n];
    __nv_bfloat16 h = __float2bfloat16(w);
    __nv_bfloat16 l = __float2bfloat16(w - __bfloat162float(h));
    g_bhi[idx] = h;
    g_blo[idx] = l;
}

// ---------------- K/V GEMM via mma.sync bf16 hi/lo split (R10 config) ----------
#define SM_AHI 0
#define SM_ALO 16384
#define SM_BHI 32768
#define SM_BLO 49152
#define SM_TOTAL 65536

__global__ __launch_bounds__(256) void k_gemm_kv_mma() {
    extern __shared__ __align__(128) char sm[];
    const int tid = threadIdx.x, wid = tid >> 5, lane = tid & 31;
    const int m0 = blockIdx.x * 128;
    const int nb = blockIdx.y;
    const int kv = nb >> 1;
    const int nloc0 = (nb & 1) * 128;
    const uint32_t smb = smem_to_u32(sm);

    const int wm = (wid >> 2) * 64;
    const int wn = (wid & 3) * 32;

    float acc[4][4][4];
#pragma unroll
    for (int i = 0; i < 4; i++)
#pragma unroll
        for (int j = 0; j < 4; j++)
#pragma unroll
            for (int t = 0; t < 4; t++) acc[i][j][t] = 0.f;

    const int ar = tid >> 1, ah = (tid & 1) * 32;
    const int brow = tid >> 1, bkh = (tid & 1) * 32;
    const float* asrc = &g_xln[(size_t)(m0 + ar) * 256 + ah];
    const __nv_bfloat16* bhsrc = &g_bhi[(size_t)(kv * 256 + nloc0 + brow) * 256 + bkh];
    const __nv_bfloat16* blsrc = &g_blo[(size_t)(kv * 256 + nloc0 + brow) * 256 + bkh];

    const int rowA = wm + (lane & 15);
    const int colAsel = (lane >> 4) * 8;
    const int rowB = wn + (lane & 7);
    const int colBsel = ((lane >> 3) & 1) * 8;

    for (int c = 0; c < 4; c++) {
#pragma unroll
        for (int i = 0; i < 8; i++) {
            float4 a = *reinterpret_cast<const float4*>(asrc + c * 64 + i * 4);
            __nv_bfloat162 h01 = __floats2bfloat162_rn(a.x, a.y);
            __nv_bfloat162 h23 = __floats2bfloat162_rn(a.z, a.w);
            float lx = a.x - __bfloat162float(h01.x);
            float ly = a.y - __bfloat162float(h01.y);
            float lz = a.z - __bfloat162float(h23.x);
            float lw = a.w - __bfloat162float(h23.y);
            __nv_bfloat162 l01 = __floats2bfloat162_rn(lx, ly);
            __nv_bfloat162 l23 = __floats2bfloat162_rn(lz, lw);
            uint32_t sw = swz(ar, (ah + i * 4) * 2);
            uint2 hv, lv;
            hv.x = *reinterpret_cast<uint32_t*>(&h01);
            hv.y = *reinterpret_cast<uint32_t*>(&h23);
            lv.x = *reinterpret_cast<uint32_t*>(&l01);
            lv.y = *reinterpret_cast<uint32_t*>(&l23);
            *reinterpret_cast<uint2*>(sm + SM_AHI + sw) = hv;
            *reinterpret_cast<uint2*>(sm + SM_ALO + sw) = lv;
        }
#pragma unroll
        for (int i = 0; i < 4; i++) {
            uint4 hv = *reinterpret_cast<const uint4*>(bhsrc + c * 64 + i * 8);
            uint4 lv = *reinterpret_cast<const uint4*>(blsrc + c * 64 + i * 8);
            uint32_t sw = swz(brow, (bkh + i * 8) * 2);
            *reinterpret_cast<uint4*>(sm + SM_BHI + sw) = hv;
            *reinterpret_cast<uint4*>(sm + SM_BLO + sw) = lv;
        }
        __syncthreads();

#pragma unroll
        for (int kk = 0; kk < 64; kk += 16) {
            uint32_t Af[4][4], Bh[4][2], Bl[4][2];
            const uint32_t colA2 = (kk + colAsel) * 2;
            const uint32_t colB2 = (kk + colBsel) * 2;
#pragma unroll
            for (int mf = 0; mf < 4; mf++)
                ldsm_x4(Af[mf], smb + SM_AHI + swz(rowA + mf * 16, colA2));
#pragma unroll
            for (int nf = 0; nf < 4; nf++)
                ldsm_x2(Bh[nf], smb + SM_BHI + swz(rowB + nf * 8, colB2));
#pragma unroll
            for (int mf = 0; mf < 4; mf++)
#pragma unroll
                for (int nf = 0; nf < 4; nf++)
                    mma16816(acc[mf][nf], Af[mf], Bh[nf]);
#pragma unroll
            for (int nf = 0; nf < 4; nf++)
                ldsm_x2(Bl[nf], smb + SM_BLO + swz(rowB + nf * 8, colB2));
#pragma unroll
            for (int mf = 0; mf < 4; mf++)
#pragma unroll
                for (int nf = 0; nf < 4; nf++)
                    mma16816(acc[mf][nf], Af[mf], Bl[nf]);
#pragma unroll
            for (int mf = 0; mf < 4; mf++)
                ldsm_x4(Af[mf], smb + SM_ALO + swz(rowA + mf * 16, colA2));
#pragma unroll
            for (int mf = 0; mf < 4; mf++)
#pragma unroll
                for (int nf = 0; nf < 4; nf++)
                    mma16816(acc[mf][nf], Af[mf], Bh[nf]);
        }
        __syncthreads();
    }

    const int g = lane >> 2, tg = lane & 3;
#pragma unroll
    for (int mf = 0; mf < 4; mf++) {
#pragma unroll
        for (int nf = 0; nf < 4; nf++) {
            int col = nb * 128 + wn + nf * 8 + tg * 2;
            __nv_bfloat16* buf = (col < 256) ? g_k : g_v;
            int c8 = col & 255;
            int h = c8 >> 6, dh = c8 & 63;
            int m = m0 + wm + mf * 16 + g;
            int b = m >> 12, n = m & 4095;
            __nv_bfloat16* dst = buf + (size_t)(((b * HEADS + h) * NTOK) + n) * DH + dh;
            __nv_bfloat162 lo = __floats2bfloat162_rn(acc[mf][nf][0], acc[mf][nf][1]);
            __nv_bfloat162 hi2 = __floats2bfloat162_rn(acc[mf][nf][2], acc[mf][nf][3]);
            *reinterpret_cast<uint32_t*>(dst) = *reinterpret_cast<uint32_t*>(&lo);
            *reinterpret_cast<uint32_t*>(dst + 8 * DH) = *reinterpret_cast<uint32_t*>(&hi2);
        }
    }
}

// ---------------- slot LN + Q projection (one block per (b,s)) ----------------
__global__ __launch_bounds__(256) void k_slot_q(const float* __restrict__ Wq,
                                                const float* __restrict__ w,
                                                const float* __restrict__ b) {
    int row = blockIdx.x;   // b*8 + s
    int j = threadIdx.x;
    __shared__ float sln[256];
    __shared__ float red[8];
    float v = g_slots[row * DIM + j];
    float s = v;
#pragma unroll
    for (int o = 16; o; o >>= 1) s += __shfl_xor_sync(~0u, s, o);
    if ((j & 31) == 0) red[j >> 5] = s;
    __syncthreads();
    float tot = 0.f;
#pragma unroll
    for (int t = 0; t < 8; t++) tot += red[t];
    float mean = tot * (1.0f / 256.0f);
    __syncthreads();
    float dv = v - mean;
    float s2 = dv * dv;
#pragma unroll
    for (int o = 16; o; o >>= 1) s2 += __shfl_xor_sync(~0u, s2, o);
    if ((j & 31) == 0) red[j >> 5] = s2;
    __syncthreads();
    float tv = 0.f;
#pragma unroll
    for (int t = 0; t < 8; t++) tv += red[t];
    sln[j] = dv * rsqrtf(tv * (1.0f / 256.0f) + 1e-5f) * w[j] + b[j];
    __syncthreads();
    float acc = 0.f;
    for (int i = 0; i < 256; i++) acc += sln[i] * Wq[i * 256 + j];
    int bb = row >> 3, sl = row & 7, h = j >> 6, dh = j & 63;
    g_q[(((bb * HEADS + h) * SLOTS) + sl) * DH + dh] = acc;
}

// ---------------- fused attention v4: HMMA (flash-attn style) -------------------
// grid (SPLIT, HEADS, BATCH), 256 threads = 8 warps. Tile = 128 tokens; warp w
// owns tokens [w*16, w*16+16) of the tile. dots: Q(16pad x 64) @ K -> C-frag;
// softmax over slots via xor{4,8,16} shuffles; P C-frag == A-frag for update mma
// (rows 8-15 zeroed); update B via ldsm.trans on V [tok][dh].
#define AT_SQ 0
#define AT_SK 2048
#define AT_SV 18432
#define AT_SU 34816          // 8 warps x 8 rows x 66 floats
#define AT_SZ 51712          // 8 warps x 8 floats
#define AT_SMEM 51968

__global__ __launch_bounds__(256) void k_attn() {
    extern __shared__ __align__(128) char sm[];
    const int chunk = blockIdx.x, h = blockIdx.y, b = blockIdx.z;
    const int tid = threadIdx.x;
    const int wid = tid >> 5;
    const int lane = tid & 31;
    const int g = lane >> 2, tg = lane & 3;
    const int bh = b * HEADS + h;
    const uint32_t smb = smem_to_u32(sm);

    // stage Q: [16][64] bf16, rows 8-15 zero, swizzled
    for (int idx = tid; idx < 1024; idx += 256) {
        int row = idx >> 6, col = idx & 63;
        float qv = (row < 8) ? g_q[bh * 512 + row * 64 + col] : 0.f;
        *reinterpret_cast<__nv_bfloat16*>(sm + AT_SQ + swz(row, col * 2)) = __float2bfloat16(qv);
    }

    const __nv_bfloat16* kbase = &g_k[(size_t)bh * NTOK * DH];
    const __nv_bfloat16* vbase = &g_v[(size_t)bh * NTOK * DH];
    const int TOK = NTOK / SPLIT;   // 512
    const int NT = TOK / 128;       // 4
    const int j0base = chunk * TOK;

    // prefetch tile 0: 128 tok x 64 dh bf16 = 16KB per array; 4 uint4/thread each
    uint4 kr[4], vr[4];
#pragma unroll
    for (int qq = 0; qq < 4; qq++) {
        int id = tid + qq * 256;
        int t = id >> 3, d8 = (id & 7) * 8;
        kr[qq] = *reinterpret_cast<const uint4*>(kbase + (size_t)(j0base + t) * DH + d8);
        vr[qq] = *reinterpret_cast<const uint4*>(vbase + (size_t)(j0base + t) * DH + d8);
    }
    __syncthreads();   // sQ visible

    // load Q A-frags once (4 k-steps)
    uint32_t Aq[4][4];
#pragma unroll
    for (int ks = 0; ks < 4; ks++)
        ldsm_x4(Aq[ks], smb + AT_SQ + swz(lane & 15, (ks * 16 + (lane >> 4) * 8) * 2));

    const int tb = wid * 16;    // warp's token base within tile
    float Uacc[8][4];
#pragma unroll
    for (int nf = 0; nf < 8; nf++)
#pragma unroll
        for (int t = 0; t < 4; t++) Uacc[nf][t] = 0.f;
    float zacc = 0.f;

    for (int tile = 0; tile < NT; tile++) {
        // store prefetched K/V tiles (swizzled, bf16, [tok][dh])
#pragma unroll
        for (int qq = 0; qq < 4; qq++) {
            int id = tid + qq * 256;
            int t = id >> 3, d8 = (id & 7) * 8;
            uint32_t sw = swz(t, d8 * 2);
            *reinterpret_cast<uint4*>(sm + AT_SK + sw) = kr[qq];
            *reinterpret_cast<uint4*>(sm + AT_SV + sw) = vr[qq];
        }
        __syncthreads();

        // prefetch next tile
        if (tile + 1 < NT) {
            const int j0n = j0base + (tile + 1) * 128;
#pragma unroll
            for (int qq = 0; qq < 4; qq++) {
                int id = tid + qq * 256;
                int t = id >> 3, d8 = (id & 7) * 8;
                kr[qq] = *reinterpret_cast<const uint4*>(kbase + (size_t)(j0n + t) * DH + d8);
                vr[qq] = *reinterpret_cast<const uint4*>(vbase + (size_t)(j0n + t) * DH + d8);
            }
        }

        // dots: D[16 slots][16 tokens] for this warp (2 n-frags x 4 k-steps)
        float D0[4] = {0.f, 0.f, 0.f, 0.f}, D1[4] = {0.f, 0.f, 0.f, 0.f};
#pragma unroll
        for (int ks = 0; ks < 4; ks++) {
            uint32_t Bk0[2], Bk1[2];
            uint32_t colb = (ks * 16 + ((lane >> 3) & 1) * 8) * 2;
            ldsm_x2(Bk0, smb + AT_SK + swz(tb + (lane & 7), colb));
            ldsm_x2(Bk1, smb + AT_SK + swz(tb + 8 + (lane & 7), colb));
            mma16816(D0, Aq[ks], Bk0);
            mma16816(D1, Aq[ks], Bk1);
        }

        // softmax over slots (rows 0-7) for the 4 tokens this lane holds
        float p00, p01, p10, p11;
        {
            float d00 = D0[0] * 0.125f, d01 = D0[1] * 0.125f;
            float d10 = D1[0] * 0.125f, d11 = D1[1] * 0.125f;
            float m00 = d00, m01 = d01, m10 = d10, m11 = d11;
#pragma unroll
            for (int o = 4; o <= 16; o <<= 1) {
                m00 = fmaxf(m00, __shfl_xor_sync(~0u, m00, o));
                m01 = fmaxf(m01, __shfl_xor_sync(~0u, m01, o));
                m10 = fmaxf(m10, __shfl_xor_sync(~0u, m10, o));
                m11 = fmaxf(m11, __shfl_xor_sync(~0u, m11, o));
            }
            float e00 = __expf(d00 - m00), e01 = __expf(d01 - m01);
            float e10 = __expf(d10 - m10), e11 = __expf(d11 - m11);
            float s00 = e00, s01 = e01, s10 = e10, s11 = e11;
#pragma unroll
            for (int o = 4; o <= 16; o <<= 1) {
                s00 += __shfl_xor_sync(~0u, s00, o);
                s01 += __shfl_xor_sync(~0u, s01, o);
                s10 += __shfl_xor_sync(~0u, s10, o);
                s11 += __shfl_xor_sync(~0u, s11, o);
            }
            p00 = e00 / s00 + 1e-8f;
            p01 = e01 / s01 + 1e-8f;
            p10 = e10 / s10 + 1e-8f;
            p11 = e11 / s11 + 1e-8f;
            zacc += p00 + p01 + p10 + p11;
        }

        // pack P as A-frag (rows 8-15 = 0): a0 = k-lo row g, a2 = k-hi row g
        uint32_t Ap[4];
        {
            __nv_bfloat162 alo = __floats2bfloat162_rn(p00, p01);
            __nv_bfloat162 ahi = __floats2bfloat162_rn(p10, p11);
            Ap[0] = *reinterpret_cast<uint32_t*>(&alo);
            Ap[1] = 0u;
            Ap[2] = *reinterpret_cast<uint32_t*>(&ahi);
            Ap[3] = 0u;
        }

        // update: U[16][64dh] += P[16][16tok] @ V; B via trans ldsm on [tok][dh]
#pragma unroll
        for (int nf = 0; nf < 8; nf++) {
            uint32_t Bv[2];
            ldsm_x2_t(Bv, smb + AT_SV + swz(tb + (lane & 15), nf * 16));
            mma16816(Uacc[nf], Ap, Bv);
        }
        __syncthreads();
    }

    // ---- deterministic cross-warp reduction ----
    float* sU = reinterpret_cast<float*>(sm + AT_SU);   // [8 warps][8 rows][66]
    float* sZ = reinterpret_cast<float*>(sm + AT_SZ);   // [8 warps][8 rows]
#pragma unroll
    for (int nf = 0; nf < 8; nf++) {
        float2 c01 = {Uacc[nf][0], Uacc[nf][1]};
        *reinterpret_cast<float2*>(&sU[(wid * 8 + g) * 66 + nf * 8 + tg * 2]) = c01;
    }
    {
        float zr = zacc;
        zr += __shfl_xor_sync(~0u, zr, 1);
        zr += __shfl_xor_sync(~0u, zr, 2);
        if (tg == 0) sZ[wid * 8 + g] = zr;
    }
    __syncthreads();

    for (int idx = tid; idx < 512; idx += 256) {
        int row = idx >> 6, dh = idx & 63;
        float s = 0.f;
#pragma unroll
        for (int w = 0; w < 8; w++) s += sU[(w * 8 + row) * 66 + dh];
        g_U[chunk][(bh * SLOTS + row) * DH + dh] = s;
    }
    if (tid < 8) {
        float s = 0.f;
#pragma unroll
        for (int w = 0; w < 8; w++) s += sZ[w * 8 + tid];
        g_Z[chunk][bh * SLOTS + tid] = s;
    }
}

// ---------------- iteration tail: Wc, GRU, LN, MLP (2 rows per block) -----------
__global__ __launch_bounds__(256) void k_tail(const float* __restrict__ Wc,
                                              const float* __restrict__ Wih,
                                              const float* __restrict__ Whh,
                                              const float* __restrict__ bih,
                                              const float* __restrict__ bhh,
                                              const float* __restrict__ lnw,
                                              const float* __restrict__ lnb,
                                              const float* __restrict__ w1,
                                              const float* __restrict__ b1,
                                              const float* __restrict__ w2,
                                              const float* __restrict__ b2,
                                              float* __restrict__ out, int write_out) {
    __shared__ float su[2][256];
    __shared__ float sc[2][256];
    __shared__ float sh[2][256];
    __shared__ float sgx[2][768];
    __shared__ float sgh[2][768];
    __shared__ float sm_[2][256];
    __shared__ float st1[2][128];
    __shared__ float smu[2], srs[2];
    const int tid = threadIdx.x;
    const int row0 = blockIdx.x * 2;

    for (int idx = tid; idx < 512; idx += 256) {
        int r = idx >> 8, j = idx & 255;
        int grow = row0 + r;
        int b = grow >> 3, s = grow & 7;
        int h = j >> 6, dh = j & 63;
        int uo = ((b * HEADS + h) * SLOTS + s) * DH + dh;
        int zo = (b * HEADS + h) * SLOTS + s;
        float uu = 0.f, zz = 0.f;
#pragma unroll
        for (int cc = 0; cc < SPLIT; cc++) {
            uu += g_U[cc][uo];
            zz += g_Z[cc][zo];
        }
        su[r][j] = uu / zz;
        sh[r][j] = g_slots[grow * DIM + j];
    }
    __syncthreads();

    {
        float a0 = 0, a1 = 0;
        for (int i2 = 0; i2 < 256; i2++) {
            float w = Wc[i2 * 256 + tid];
            a0 += su[0][i2] * w;
            a1 += su[1][i2] * w;
        }
        sc[0][tid] = a0; sc[1][tid] = a1;
    }
    __syncthreads();

    {
        int w = tid >> 5, l = tid & 31;
        for (int r = w; r < 768; r += 8) {
            float ax0 = 0, ax1 = 0, ah0 = 0, ah1 = 0;
            const float* wi = &Wih[r * 256];
            const float* wh = &Whh[r * 256];
#pragma unroll
            for (int t = 0; t < 8; t++) {
                int ii = l + 32 * t;
                float wiv = wi[ii], whv = wh[ii];
                ax0 += sc[0][ii] * wiv; ah0 += sh[0][ii] * whv;
                ax1 += sc[1][ii] * wiv; ah1 += sh[1][ii] * whv;
            }
#pragma unroll
            for (int o = 16; o; o >>= 1) {
                ax0 += __shfl_xor_sync(~0u, ax0, o); ax1 += __shfl_xor_sync(~0u, ax1, o);
                ah0 += __shfl_xor_sync(~0u, ah0, o); ah1 += __shfl_xor_sync(~0u, ah1, o);
            }
            if (l == 0) {
                float bi = bih[r], bh2 = bhh[r];
                sgx[0][r] = ax0 + bi; sgx[1][r] = ax1 + bi;
                sgh[0][r] = ah0 + bh2; sgh[1][r] = ah1 + bh2;
            }
        }
    }
    __syncthreads();

    {
        int d = tid;
#pragma unroll
        for (int r = 0; r < 2; r++) {
            float rr = 1.f / (1.f + __expf(-(sgx[r][d] + sgh[r][d])));
            float zz = 1.f / (1.f + __expf(-(sgx[r][256 + d] + sgh[r][256 + d])));
            float nn = tanhf(sgx[r][512 + d] + rr * sgh[r][512 + d]);
            su[r][d] = (1.f - zz) * nn + zz * sh[r][d];
        }
    }
    __syncthreads();

    {
        int w = tid >> 5, l = tid & 31;
        if (w < 2) {
            float s1 = 0.f;
#pragma unroll
            for (int t = 0; t < 8; t++) s1 += su[w][l + 32 * t];
#pragma unroll
            for (int o = 16; o; o >>= 1) s1 += __shfl_xor_sync(~0u, s1, o);
            float mean = s1 * (1.0f / 256.0f);
            float s2 = 0.f;
#pragma unroll
            for (int t = 0; t < 8; t++) {
                float dd = su[w][l + 32 * t] - mean;
                s2 += dd * dd;
            }
#pragma unroll
            for (int o = 16; o; o >>= 1) s2 += __shfl_xor_sync(~0u, s2, o);
            if (l == 0) { smu[w] = mean; srs[w] = rsqrtf(s2 * (1.0f / 256.0f) + 1e-5f); }
        }
    }
    __syncthreads();
    {
        int d = tid;
        float lw = lnw[d], lb = lnb[d];
#pragma unroll
        for (int r = 0; r < 2; r++)
            sm_[r][d] = (su[r][d] - smu[r]) * srs[r] * lw + lb;
    }
    __syncthreads();

    {
        int k = tid & 127;
        int r = tid >> 7;
        float a0 = 0;
        for (int d2 = 0; d2 < 256; d2++)
            a0 += sm_[r][d2] * w1[d2 * 128 + k];
        st1[r][k] = fmaxf(a0 + b1[k], 0.f);
    }
    __syncthreads();

    {
        int d = tid;
        float a0 = 0, a1 = 0;
        for (int k2 = 0; k2 < 128; k2++) {
            float w = w2[k2 * 256 + d];
            a0 += st1[0][k2] * w;
            a1 += st1[1][k2] * w;
        }
        float bb2 = b2[d];
        float o0 = su[0][d] + a0 + bb2, o1 = su[1][d] + a1 + bb2;
        g_slots[(row0 + 0) * DIM + d] = o0;
        g_slots[(row0 + 1) * DIM + d] = o1;
        if (write_out) {
            out[(row0 + 0) * DIM + d] = o0;
            out[(row0 + 1) * DIM + d] = o1;
        }
    }
}

// ---------------- launch ----------------
extern "C" void kernel_launch(void* const* d_in, const int* in_sizes, int n_in,
                              void* d_out, int out_size) {
    const float* inputs  = (const float*)d_in[0];
    const float* mu      = (const float*)d_in[1];
    const float* lsig    = (const float*)d_in[2];
    const float* ln_in_w = (const float*)d_in[3];
    const float* ln_in_b = (const float*)d_in[4];
    const float* ln_s_w  = (const float*)d_in[5];
    const float* ln_s_b  = (const float*)d_in[6];
    const float* Wq      = (const float*)d_in[7];
    const float* Wk      = (const float*)d_in[8];
    const float* Wv      = (const float*)d_in[9];
    const float* Wc      = (const float*)d_in[10];
    const float* Wih     = (const float*)d_in[11];
    const float* Whh     = (const float*)d_in[12];
    const float* bih     = (const float*)d_in[13];
    const float* bhh     = (const float*)d_in[14];
    const float* lnmw    = (const float*)d_in[15];
    const float* lnmb    = (const float*)d_in[16];
    const float* w1      = (const float*)d_in[17];
    const float* b1      = (const float*)d_in[18];
    const float* w2      = (const float*)d_in[19];
    const float* b2      = (const float*)d_in[20];
    float* out = (float*)d_out;

    cudaFuncSetAttribute(k_gemm_kv_mma, cudaFuncAttributeMaxDynamicSharedMemorySize, SM_TOTAL);
    cudaFuncSetAttribute(k_attn, cudaFuncAttributeMaxDynamicSharedMemorySize, AT_SMEM);

    k_init_slots<<<256, 256>>>(mu, lsig);
    k_prep_w<<<512, 256>>>(Wk, Wv);
    k_ln_in<<<BATCH * NTOK / 8, 256>>>(inputs, ln_in_w, ln_in_b);
    k_gemm_kv_mma<<<dim3(BATCH * NTOK / 128, 4), 256, SM_TOTAL>>>();

    for (int it = 0; it < ITERS; it++) {
        k_slot_q<<<BATCH * SLOTS, 256>>>(Wq, ln_s_w, ln_s_b);
        k_attn<<<dim3(SPLIT, HEADS, BATCH), 256, AT_SMEM>>>();
        k_tail<<<BATCH * SLOTS / 2, 256>>>(Wc, Wih, Whh, bih, bhh,
                                           lnmw, lnmb, w1, b1, w2, b2,
                                           out, it == ITERS - 1 ? 1 : 0);
    }
}

// round 17
// speedup vs baseline: 1.3780x; 1.0035x over previous
#include <cuda_runtime.h>
#include <cuda_bf16.h>
#include <cstdint>

#define BATCH 32
#define NTOK  4096
#define DIM   256
#define HEADS 4
#define DH    64
#define SLOTS 8
#define ITERS 3
#define SPLIT 8   // token chunks per (b,h) in attention

// ---------------- scratch (static device memory; no allocations) ----------------
__device__ float g_xln[BATCH * NTOK * DIM];             // LayerNorm'd inputs
__device__ __nv_bfloat16 g_k[BATCH * HEADS * NTOK * DH]; // (b,h,n,dh) bf16
__device__ __nv_bfloat16 g_v[BATCH * HEADS * NTOK * DH]; // (b,h,n,dh) bf16
__device__ float g_q[BATCH * HEADS * SLOTS * DH];       // (b,h,s,dh)
__device__ float g_slots[BATCH * SLOTS * DIM];          // current slots
__device__ float g_U[SPLIT][BATCH * HEADS * SLOTS * DH];// partial weighted V sums
__device__ float g_Z[SPLIT][BATCH * HEADS * SLOTS];     // partial attn mass
// transposed bf16 hi/lo weights: [kv][n (256)][k (256)]
__device__ __nv_bfloat16 g_bhi[2 * 256 * 256];
__device__ __nv_bfloat16 g_blo[2 * 256 * 256];

// ---------------- mma.sync helpers (base sm_103 PTX, no "a" features) ----------
__device__ __forceinline__ uint32_t smem_to_u32(const void* p) {
    uint32_t a;
    asm("{ .reg .u64 t; cvta.to.shared.u64 t, %1; cvt.u32.u64 %0, t; }" : "=r"(a) : "l"(p));
    return a;
}
__device__ __forceinline__ void ldsm_x4(uint32_t* r, uint32_t addr) {
    asm volatile("ldmatrix.sync.aligned.m8n8.x4.shared.b16 {%0,%1,%2,%3}, [%4];"
        : "=r"(r[0]), "=r"(r[1]), "=r"(r[2]), "=r"(r[3]) : "r"(addr));
}
// non-trans: smem [n][k] (k contiguous) -> m16n8k16 B fragment
__device__ __forceinline__ void ldsm_x2(uint32_t* r, uint32_t addr) {
    asm volatile("ldmatrix.sync.aligned.m8n8.x2.shared.b16 {%0,%1}, [%2];"
        : "=r"(r[0]), "=r"(r[1]) : "r"(addr));
}
// trans: smem [k][n] (n contiguous) -> m16n8k16 B fragment (flash-attn V path)
__device__ __forceinline__ void ldsm_x2_t(uint32_t* r, uint32_t addr) {
    asm volatile("ldmatrix.sync.aligned.m8n8.x2.trans.shared.b16 {%0,%1}, [%2];"
        : "=r"(r[0]), "=r"(r[1]) : "r"(addr));
}
__device__ __forceinline__ void mma16816(float* c, const uint32_t* a, const uint32_t* b) {
    asm volatile("mma.sync.aligned.m16n8k16.row.col.f32.bf16.bf16.f32 "
        "{%0,%1,%2,%3}, {%4,%5,%6,%7}, {%8,%9}, {%0,%1,%2,%3};"
        : "+f"(c[0]), "+f"(c[1]), "+f"(c[2]), "+f"(c[3])
        : "r"(a[0]), "r"(a[1]), "r"(a[2]), "r"(a[3]), "r"(b[0]), "r"(b[1]));
}
// XOR swizzle: rows of 128B, 16B chunks, chunk ^= (row & 7)
__device__ __forceinline__ uint32_t swz(uint32_t row, uint32_t kbyte) {
    return row * 128 + ((((kbyte >> 4) ^ (row & 7)) << 4) | (kbyte & 15));
}

// ---------------- slot init: Threefry2x32, JAX partitionable path, key(42) ------
__device__ __forceinline__ unsigned rotl32(unsigned x, int r) {
    return __funnelshift_l(x, x, r);
}

__global__ __launch_bounds__(256) void k_init_slots(const float* __restrict__ mu,
                                                    const float* __restrict__ lsig) {
    unsigned idx = blockIdx.x * blockDim.x + threadIdx.x;  // 0..65535
    if (idx >= 65536u) return;
    const unsigned K0 = 0u, K1 = 42u, K2 = 0x1BD11BDAu ^ 0u ^ 42u;
    unsigned x0 = 0u, x1 = idx;
    x0 += K0; x1 += K1;
#define TFR(r) { x0 += x1; x1 = rotl32(x1, r); x1 ^= x0; }
    TFR(13) TFR(15) TFR(26) TFR(6)
    x0 += K1; x1 += K2 + 1u;
    TFR(17) TFR(29) TFR(16) TFR(24)
    x0 += K2; x1 += K0 + 2u;
    TFR(13) TFR(15) TFR(26) TFR(6)
    x0 += K0; x1 += K1 + 3u;
    TFR(17) TFR(29) TFR(16) TFR(24)
    x0 += K1; x1 += K2 + 4u;
    TFR(13) TFR(15) TFR(26) TFR(6)
    x0 += K2; x1 += K0 + 5u;
#undef TFR
    unsigned bits = x0 ^ x1;
    const float LO = -0.99999994f;
    float f = __uint_as_float((bits >> 9) | 0x3F800000u) - 1.0f;
    float u = fmaxf(LO, f * 2.0f + LO);
    float nz = 1.41421356237309515f * erfinvf(u);
    int d = idx & 255;
    g_slots[idx] = mu[d] + expf(lsig[d]) * nz;
}

// ---------------- LayerNorm of inputs: one WARP per row, no block barriers ------
__global__ __launch_bounds__(256) void k_ln_in(const float* __restrict__ x,
                                               const float* __restrict__ w,
                                               const float* __restrict__ b) {
    const int wid = threadIdx.x >> 5, lane = threadIdx.x & 31;
    const int row = blockIdx.x * 8 + wid;
    const float* src = x + (size_t)row * DIM + lane * 8;
    float4 a0 = *reinterpret_cast<const float4*>(src);
    float4 a1 = *reinterpret_cast<const float4*>(src + 4);
    float s = a0.x + a0.y + a0.z + a0.w + a1.x + a1.y + a1.z + a1.w;
#pragma unroll
    for (int o = 16; o; o >>= 1) s += __shfl_xor_sync(~0u, s, o);
    float mean = s * (1.0f / 256.0f);
    float d0 = a0.x - mean, d1 = a0.y - mean, d2 = a0.z - mean, d3 = a0.w - mean;
    float d4 = a1.x - mean, d5 = a1.y - mean, d6 = a1.z - mean, d7 = a1.w - mean;
    float s2 = d0*d0 + d1*d1 + d2*d2 + d3*d3 + d4*d4 + d5*d5 + d6*d6 + d7*d7;
#pragma unroll
    for (int o = 16; o; o >>= 1) s2 += __shfl_xor_sync(~0u, s2, o);
    float rs = rsqrtf(s2 * (1.0f / 256.0f) + 1e-5f);
    const float4 w0 = *reinterpret_cast<const float4*>(w + lane * 8);
    const float4 w1 = *reinterpret_cast<const float4*>(w + lane * 8 + 4);
    const float4 b0 = *reinterpret_cast<const float4*>(b + lane * 8);
    const float4 b1 = *reinterpret_cast<const float4*>(b + lane * 8 + 4);
    float4 o0, o1;
    o0.x = d0 * rs * w0.x + b0.x; o0.y = d1 * rs * w0.y + b0.y;
    o0.z = d2 * rs * w0.z + b0.z; o0.w = d3 * rs * w0.w + b0.w;
    o1.x = d4 * rs * w1.x + b1.x; o1.y = d5 * rs * w1.y + b1.y;
    o1.z = d6 * rs * w1.z + b1.z; o1.w = d7 * rs * w1.w + b1.w;
    float* dst = g_xln + (size_t)row * DIM + lane * 8;
    *reinterpret_cast<float4*>(dst) = o0;
    *reinterpret_cast<float4*>(dst + 4) = o1;
}

// ---------------- weight prep: W^T -> bf16 hi/lo ----------------
__global__ __launch_bounds__(256) void k_prep_w(const float* __restrict__ Wk,
                                                const float* __restrict__ Wv) {
    int idx = blockIdx.x * 256 + threadIdx.x;   // 0..131071
    int kv = idx >> 16;
    int rest = idx & 65535;
    int n = rest >> 8, k = rest & 255;
    float w = (kv ? Wv : Wk)[k * 256 + n];
    __nv_bfloat16 h = __float2bfloat16(w);
    __nv_bfloat16 l = __float2bfloat16(w - __bfloat162float(h));
    g_bhi[idx] = h;
    g_blo[idx] = l;
}

// ---------------- K/V GEMM via mma.sync bf16 hi/lo split -----------------------
// grid (4, 1024): x = 128-col tile of [Wk|Wv] (FAST dim -> the 4 CTAs sharing an
// A-tile are launch-adjacent and co-resident => A reads hit L2), y = M-tile.
#define SM_AHI 0
#define SM_ALO 16384
#define SM_BHI 32768
#define SM_BLO 49152
#define SM_TOTAL 65536

__global__ __launch_bounds__(256) void k_gemm_kv_mma() {
    extern __shared__ __align__(128) char sm[];
    const int tid = threadIdx.x, wid = tid >> 5, lane = tid & 31;
    const int m0 = blockIdx.y * 128;
    const int nb = blockIdx.x;
    const int kv = nb >> 1;
    const int nloc0 = (nb & 1) * 128;
    const uint32_t smb = smem_to_u32(sm);

    const int wm = (wid >> 2) * 64;
    const int wn = (wid & 3) * 32;

    float acc[4][4][4];
#pragma unroll
    for (int i = 0; i < 4; i++)
#pragma unroll
        for (int j = 0; j < 4; j++)
#pragma unroll
            for (int t = 0; t < 4; t++) acc[i][j][t] = 0.f;

    const int ar = tid >> 1, ah = (tid & 1) * 32;
    const int brow = tid >> 1, bkh = (tid & 1) * 32;
    const float* asrc = &g_xln[(size_t)(m0 + ar) * 256 + ah];
    const __nv_bfloat16* bhsrc = &g_bhi[(size_t)(kv * 256 + nloc0 + brow) * 256 + bkh];
    const __nv_bfloat16* blsrc = &g_blo[(size_t)(kv * 256 + nloc0 + brow) * 256 + bkh];

    const int rowA = wm + (lane & 15);
    const int colAsel = (lane >> 4) * 8;
    const int rowB = wn + (lane & 7);
    const int colBsel = ((lane >> 3) & 1) * 8;

    for (int c = 0; c < 4; c++) {
#pragma unroll
        for (int i = 0; i < 8; i++) {
            float4 a = *reinterpret_cast<const float4*>(asrc + c * 64 + i * 4);
            __nv_bfloat162 h01 = __floats2bfloat162_rn(a.x, a.y);
            __nv_bfloat162 h23 = __floats2bfloat162_rn(a.z, a.w);
            float lx = a.x - __bfloat162float(h01.x);
            float ly = a.y - __bfloat162float(h01.y);
            float lz = a.z - __bfloat162float(h23.x);
            float lw = a.w - __bfloat162float(h23.y);
            __nv_bfloat162 l01 = __floats2bfloat162_rn(lx, ly);
            __nv_bfloat162 l23 = __floats2bfloat162_rn(lz, lw);
            uint32_t sw = swz(ar, (ah + i * 4) * 2);
            uint2 hv, lv;
            hv.x = *reinterpret_cast<uint32_t*>(&h01);
            hv.y = *reinterpret_cast<uint32_t*>(&h23);
            lv.x = *reinterpret_cast<uint32_t*>(&l01);
            lv.y = *reinterpret_cast<uint32_t*>(&l23);
            *reinterpret_cast<uint2*>(sm + SM_AHI + sw) = hv;
            *reinterpret_cast<uint2*>(sm + SM_ALO + sw) = lv;
        }
#pragma unroll
        for (int i = 0; i < 4; i++) {
            uint4 hv = *reinterpret_cast<const uint4*>(bhsrc + c * 64 + i * 8);
            uint4 lv = *reinterpret_cast<const uint4*>(blsrc + c * 64 + i * 8);
            uint32_t sw = swz(brow, (bkh + i * 8) * 2);
            *reinterpret_cast<uint4*>(sm + SM_BHI + sw) = hv;
            *reinterpret_cast<uint4*>(sm + SM_BLO + sw) = lv;
        }
        __syncthreads();

#pragma unroll
        for (int kk = 0; kk < 64; kk += 16) {
            uint32_t Af[4][4], Bh[4][2], Bl[4][2];
            const uint32_t colA2 = (kk + colAsel) * 2;
            const uint32_t colB2 = (kk + colBsel) * 2;
#pragma unroll
            for (int mf = 0; mf < 4; mf++)
                ldsm_x4(Af[mf], smb + SM_AHI + swz(rowA + mf * 16, colA2));
#pragma unroll
            for (int nf = 0; nf < 4; nf++)
                ldsm_x2(Bh[nf], smb + SM_BHI + swz(rowB + nf * 8, colB2));
#pragma unroll
            for (int mf = 0; mf < 4; mf++)
#pragma unroll
                for (int nf = 0; nf < 4; nf++)
                    mma16816(acc[mf][nf], Af[mf], Bh[nf]);
#pragma unroll
            for (int nf = 0; nf < 4; nf++)
                ldsm_x2(Bl[nf], smb + SM_BLO + swz(rowB + nf * 8, colB2));
#pragma unroll
            for (int mf = 0; mf < 4; mf++)
#pragma unroll
                for (int nf = 0; nf < 4; nf++)
                    mma16816(acc[mf][nf], Af[mf], Bl[nf]);
#pragma unroll
            for (int mf = 0; mf < 4; mf++)
                ldsm_x4(Af[mf], smb + SM_ALO + swz(rowA + mf * 16, colA2));
#pragma unroll
            for (int mf = 0; mf < 4; mf++)
#pragma unroll
                for (int nf = 0; nf < 4; nf++)
                    mma16816(acc[mf][nf], Af[mf], Bh[nf]);
        }
        __syncthreads();
    }

    const int g = lane >> 2, tg = lane & 3;
#pragma unroll
    for (int mf = 0; mf < 4; mf++) {
#pragma unroll
        for (int nf = 0; nf < 4; nf++) {
            int col = nb * 128 + wn + nf * 8 + tg * 2;
            __nv_bfloat16* buf = (col < 256) ? g_k : g_v;
            int c8 = col & 255;
            int h = c8 >> 6, dh = c8 & 63;
            int m = m0 + wm + mf * 16 + g;
            int b = m >> 12, n = m & 4095;
            __nv_bfloat16* dst = buf + (size_t)(((b * HEADS + h) * NTOK) + n) * DH + dh;
            __nv_bfloat162 lo = __floats2bfloat162_rn(acc[mf][nf][0], acc[mf][nf][1]);
            __nv_bfloat162 hi2 = __floats2bfloat162_rn(acc[mf][nf][2], acc[mf][nf][3]);
            *reinterpret_cast<uint32_t*>(dst) = *reinterpret_cast<uint32_t*>(&lo);
            *reinterpret_cast<uint32_t*>(dst + 8 * DH) = *reinterpret_cast<uint32_t*>(&hi2);
        }
    }
}

// ---------------- slot LN + Q projection (one block per (b,s)) ----------------
__global__ __launch_bounds__(256) void k_slot_q(const float* __restrict__ Wq,
                                                const float* __restrict__ w,
                                                const float* __restrict__ b) {
    int row = blockIdx.x;   // b*8 + s
    int j = threadIdx.x;
    __shared__ float sln[256];
    __shared__ float red[8];
    float v = g_slots[row * DIM + j];
    float s = v;
#pragma unroll
    for (int o = 16; o; o >>= 1) s += __shfl_xor_sync(~0u, s, o);
    if ((j & 31) == 0) red[j >> 5] = s;
    __syncthreads();
    float tot = 0.f;
#pragma unroll
    for (int t = 0; t < 8; t++) tot += red[t];
    float mean = tot * (1.0f / 256.0f);
    __syncthreads();
    float dv = v - mean;
    float s2 = dv * dv;
#pragma unroll
    for (int o = 16; o; o >>= 1) s2 += __shfl_xor_sync(~0u, s2, o);
    if ((j & 31) == 0) red[j >> 5] = s2;
    __syncthreads();
    float tv = 0.f;
#pragma unroll
    for (int t = 0; t < 8; t++) tv += red[t];
    sln[j] = dv * rsqrtf(tv * (1.0f / 256.0f) + 1e-5f) * w[j] + b[j];
    __syncthreads();
    float acc = 0.f;
    for (int i = 0; i < 256; i++) acc += sln[i] * Wq[i * 256 + j];
    int bb = row >> 3, sl = row & 7, h = j >> 6, dh = j & 63;
    g_q[(((bb * HEADS + h) * SLOTS) + sl) * DH + dh] = acc;
}

// ---------------- fused attention v4: HMMA (flash-attn style) -------------------
#define AT_SQ 0
#define AT_SK 2048
#define AT_SV 18432
#define AT_SU 34816          // 8 warps x 8 rows x 66 floats
#define AT_SZ 51712          // 8 warps x 8 floats
#define AT_SMEM 51968

__global__ __launch_bounds__(256) void k_attn() {
    extern __shared__ __align__(128) char sm[];
    const int chunk = blockIdx.x, h = blockIdx.y, b = blockIdx.z;
    const int tid = threadIdx.x;
    const int wid = tid >> 5;
    const int lane = tid & 31;
    const int g = lane >> 2, tg = lane & 3;
    const int bh = b * HEADS + h;
    const uint32_t smb = smem_to_u32(sm);

    // stage Q: [16][64] bf16, rows 8-15 zero, swizzled
    for (int idx = tid; idx < 1024; idx += 256) {
        int row = idx >> 6, col = idx & 63;
        float qv = (row < 8) ? g_q[bh * 512 + row * 64 + col] : 0.f;
        *reinterpret_cast<__nv_bfloat16*>(sm + AT_SQ + swz(row, col * 2)) = __float2bfloat16(qv);
    }

    const __nv_bfloat16* kbase = &g_k[(size_t)bh * NTOK * DH];
    const __nv_bfloat16* vbase = &g_v[(size_t)bh * NTOK * DH];
    const int TOK = NTOK / SPLIT;   // 512
    const int NT = TOK / 128;       // 4
    const int j0base = chunk * TOK;

    uint4 kr[4], vr[4];
#pragma unroll
    for (int qq = 0; qq < 4; qq++) {
        int id = tid + qq * 256;
        int t = id >> 3, d8 = (id & 7) * 8;
        kr[qq] = *reinterpret_cast<const uint4*>(kbase + (size_t)(j0base + t) * DH + d8);
        vr[qq] = *reinterpret_cast<const uint4*>(vbase + (size_t)(j0base + t) * DH + d8);
    }
    __syncthreads();   // sQ visible

    uint32_t Aq[4][4];
#pragma unroll
    for (int ks = 0; ks < 4; ks++)
        ldsm_x4(Aq[ks], smb + AT_SQ + swz(lane & 15, (ks * 16 + (lane >> 4) * 8) * 2));

    const int tb = wid * 16;
    float Uacc[8][4];
#pragma unroll
    for (int nf = 0; nf < 8; nf++)
#pragma unroll
        for (int t = 0; t < 4; t++) Uacc[nf][t] = 0.f;
    float zacc = 0.f;

    for (int tile = 0; tile < NT; tile++) {
#pragma unroll
        for (int qq = 0; qq < 4; qq++) {
            int id = tid + qq * 256;
            int t = id >> 3, d8 = (id & 7) * 8;
            uint32_t sw = swz(t, d8 * 2);
            *reinterpret_cast<uint4*>(sm + AT_SK + sw) = kr[qq];
            *reinterpret_cast<uint4*>(sm + AT_SV + sw) = vr[qq];
        }
        __syncthreads();

        if (tile + 1 < NT) {
            const int j0n = j0base + (tile + 1) * 128;
#pragma unroll
            for (int qq = 0; qq < 4; qq++) {
                int id = tid + qq * 256;
                int t = id >> 3, d8 = (id & 7) * 8;
                kr[qq] = *reinterpret_cast<const uint4*>(kbase + (size_t)(j0n + t) * DH + d8);
                vr[qq] = *reinterpret_cast<const uint4*>(vbase + (size_t)(j0n + t) * DH + d8);
            }
        }

        float D0[4] = {0.f, 0.f, 0.f, 0.f}, D1[4] = {0.f, 0.f, 0.f, 0.f};
#pragma unroll
        for (int ks = 0; ks < 4; ks++) {
            uint32_t Bk0[2], Bk1[2];
            uint32_t colb = (ks * 16 + ((lane >> 3) & 1) * 8) * 2;
            ldsm_x2(Bk0, smb + AT_SK + swz(tb + (lane & 7), colb));
            ldsm_x2(Bk1, smb + AT_SK + swz(tb + 8 + (lane & 7), colb));
            mma16816(D0, Aq[ks], Bk0);
            mma16816(D1, Aq[ks], Bk1);
        }

        float p00, p01, p10, p11;
        {
            float d00 = D0[0] * 0.125f, d01 = D0[1] * 0.125f;
            float d10 = D1[0] * 0.125f, d11 = D1[1] * 0.125f;
            float m00 = d00, m01 = d01, m10 = d10, m11 = d11;
#pragma unroll
            for (int o = 4; o <= 16; o <<= 1) {
                m00 = fmaxf(m00, __shfl_xor_sync(~0u, m00, o));
                m01 = fmaxf(m01, __shfl_xor_sync(~0u, m01, o));
                m10 = fmaxf(m10, __shfl_xor_sync(~0u, m10, o));
                m11 = fmaxf(m11, __shfl_xor_sync(~0u, m11, o));
            }
            float e00 = __expf(d00 - m00), e01 = __expf(d01 - m01);
            float e10 = __expf(d10 - m10), e11 = __expf(d11 - m11);
            float s00 = e00, s01 = e01, s10 = e10, s11 = e11;
#pragma unroll
            for (int o = 4; o <= 16; o <<= 1) {
                s00 += __shfl_xor_sync(~0u, s00, o);
                s01 += __shfl_xor_sync(~0u, s01, o);
                s10 += __shfl_xor_sync(~0u, s10, o);
                s11 += __shfl_xor_sync(~0u, s11, o);
            }
            p00 = e00 / s00 + 1e-8f;
            p01 = e01 / s01 + 1e-8f;
            p10 = e10 / s10 + 1e-8f;
            p11 = e11 / s11 + 1e-8f;
            zacc += p00 + p01 + p10 + p11;
        }

        uint32_t Ap[4];
        {
            __nv_bfloat162 alo = __floats2bfloat162_rn(p00, p01);
            __nv_bfloat162 ahi = __floats2bfloat162_rn(p10, p11);
            Ap[0] = *reinterpret_cast<uint32_t*>(&alo);
            Ap[1] = 0u;
            Ap[2] = *reinterpret_cast<uint32_t*>(&ahi);
            Ap[3] = 0u;
        }

#pragma unroll
        for (int nf = 0; nf < 8; nf++) {
            uint32_t Bv[2];
            ldsm_x2_t(Bv, smb + AT_SV + swz(tb + (lane & 15), nf * 16));
            mma16816(Uacc[nf], Ap, Bv);
        }
        __syncthreads();
    }

    float* sU = reinterpret_cast<float*>(sm + AT_SU);
    float* sZ = reinterpret_cast<float*>(sm + AT_SZ);
#pragma unroll
    for (int nf = 0; nf < 8; nf++) {
        float2 c01 = {Uacc[nf][0], Uacc[nf][1]};
        *reinterpret_cast<float2*>(&sU[(wid * 8 + g) * 66 + nf * 8 + tg * 2]) = c01;
    }
    {
        float zr = zacc;
        zr += __shfl_xor_sync(~0u, zr, 1);
        zr += __shfl_xor_sync(~0u, zr, 2);
        if (tg == 0) sZ[wid * 8 + g] = zr;
    }
    __syncthreads();

    for (int idx = tid; idx < 512; idx += 256) {
        int row = idx >> 6, dh = idx & 63;
        float s = 0.f;
#pragma unroll
        for (int w = 0; w < 8; w++) s += sU[(w * 8 + row) * 66 + dh];
        g_U[chunk][(bh * SLOTS + row) * DH + dh] = s;
    }
    if (tid < 8) {
        float s = 0.f;
#pragma unroll
        for (int w = 0; w < 8; w++) s += sZ[w * 8 + tid];
        g_Z[chunk][bh * SLOTS + tid] = s;
    }
}

// ---------------- iteration tail: Wc, GRU, LN, MLP (2 rows per block) -----------
__global__ __launch_bounds__(256) void k_tail(const float* __restrict__ Wc,
                                              const float* __restrict__ Wih,
                                              const float* __restrict__ Whh,
                                              const float* __restrict__ bih,
                                              const float* __restrict__ bhh,
                                              const float* __restrict__ lnw,
                                              const float* __restrict__ lnb,
                                              const float* __restrict__ w1,
                                              const float* __restrict__ b1,
                                              const float* __restrict__ w2,
                                              const float* __restrict__ b2,
                                              float* __restrict__ out, int write_out) {
    __shared__ float su[2][256];
    __shared__ float sc[2][256];
    __shared__ float sh[2][256];
    __shared__ float sgx[2][768];
    __shared__ float sgh[2][768];
    __shared__ float sm_[2][256];
    __shared__ float st1[2][128];
    __shared__ float smu[2], srs[2];
    const int tid = threadIdx.x;
    const int row0 = blockIdx.x * 2;

    for (int idx = tid; idx < 512; idx += 256) {
        int r = idx >> 8, j = idx & 255;
        int grow = row0 + r;
        int b = grow >> 3, s = grow & 7;
        int h = j >> 6, dh = j & 63;
        int uo = ((b * HEADS + h) * SLOTS + s) * DH + dh;
        int zo = (b * HEADS + h) * SLOTS + s;
        float uu = 0.f, zz = 0.f;
#pragma unroll
        for (int cc = 0; cc < SPLIT; cc++) {
            uu += g_U[cc][uo];
            zz += g_Z[cc][zo];
        }
        su[r][j] = uu / zz;
        sh[r][j] = g_slots[grow * DIM + j];
    }
    __syncthreads();

    {
        float a0 = 0, a1 = 0;
        for (int i2 = 0; i2 < 256; i2++) {
            float w = Wc[i2 * 256 + tid];
            a0 += su[0][i2] * w;
            a1 += su[1][i2] * w;
        }
        sc[0][tid] = a0; sc[1][tid] = a1;
    }
    __syncthreads();

    {
        int w = tid >> 5, l = tid & 31;
        for (int r = w; r < 768; r += 8) {
            float ax0 = 0, ax1 = 0, ah0 = 0, ah1 = 0;
            const float* wi = &Wih[r * 256];
            const float* wh = &Whh[r * 256];
#pragma unroll
            for (int t = 0; t < 8; t++) {
                int ii = l + 32 * t;
                float wiv = wi[ii], whv = wh[ii];
                ax0 += sc[0][ii] * wiv; ah0 += sh[0][ii] * whv;
                ax1 += sc[1][ii] * wiv; ah1 += sh[1][ii] * whv;
            }
#pragma unroll
            for (int o = 16; o; o >>= 1) {
                ax0 += __shfl_xor_sync(~0u, ax0, o); ax1 += __shfl_xor_sync(~0u, ax1, o);
                ah0 += __shfl_xor_sync(~0u, ah0, o); ah1 += __shfl_xor_sync(~0u, ah1, o);
            }
            if (l == 0) {
                float bi = bih[r], bh2 = bhh[r];
                sgx[0][r] = ax0 + bi; sgx[1][r] = ax1 + bi;
                sgh[0][r] = ah0 + bh2; sgh[1][r] = ah1 + bh2;
            }
        }
    }
    __syncthreads();

    {
        int d = tid;
#pragma unroll
        for (int r = 0; r < 2; r++) {
            float rr = 1.f / (1.f + __expf(-(sgx[r][d] + sgh[r][d])));
            float zz = 1.f / (1.f + __expf(-(sgx[r][256 + d] + sgh[r][256 + d])));
            float nn = tanhf(sgx[r][512 + d] + rr * sgh[r][512 + d]);
            su[r][d] = (1.f - zz) * nn + zz * sh[r][d];
        }
    }
    __syncthreads();

    {
        int w = tid >> 5, l = tid & 31;
        if (w < 2) {
            float s1 = 0.f;
#pragma unroll
            for (int t = 0; t < 8; t++) s1 += su[w][l + 32 * t];
#pragma unroll
            for (int o = 16; o; o >>= 1) s1 += __shfl_xor_sync(~0u, s1, o);
            float mean = s1 * (1.0f / 256.0f);
            float s2 = 0.f;
#pragma unroll
            for (int t = 0; t < 8; t++) {
                float dd = su[w][l + 32 * t] - mean;
                s2 += dd * dd;
            }
#pragma unroll
            for (int o = 16; o; o >>= 1) s2 += __shfl_xor_sync(~0u, s2, o);
            if (l == 0) { smu[w] = mean; srs[w] = rsqrtf(s2 * (1.0f / 256.0f) + 1e-5f); }
        }
    }
    __syncthreads();
    {
        int d = tid;
        float lw = lnw[d], lb = lnb[d];
#pragma unroll
        for (int r = 0; r < 2; r++)
            sm_[r][d] = (su[r][d] - smu[r]) * srs[r] * lw + lb;
    }
    __syncthreads();

    {
        int k = tid & 127;
        int r = tid >> 7;
        float a0 = 0;
        for (int d2 = 0; d2 < 256; d2++)
            a0 += sm_[r][d2] * w1[d2 * 128 + k];
        st1[r][k] = fmaxf(a0 + b1[k], 0.f);
    }
    __syncthreads();

    {
        int d = tid;
        float a0 = 0, a1 = 0;
        for (int k2 = 0; k2 < 128; k2++) {
            float w = w2[k2 * 256 + d];
            a0 += st1[0][k2] * w;
            a1 += st1[1][k2] * w;
        }
        float bb2 = b2[d];
        float o0 = su[0][d] + a0 + bb2, o1 = su[1][d] + a1 + bb2;
        g_slots[(row0 + 0) * DIM + d] = o0;
        g_slots[(row0 + 1) * DIM + d] = o1;
        if (write_out) {
            out[(row0 + 0) * DIM + d] = o0;
            out[(row0 + 1) * DIM + d] = o1;
        }
    }
}

// ---------------- launch ----------------
extern "C" void kernel_launch(void* const* d_in, const int* in_sizes, int n_in,
                              void* d_out, int out_size) {
    const float* inputs  = (const float*)d_in[0];
    const float* mu      = (const float*)d_in[1];
    const float* lsig    = (const float*)d_in[2];
    const float* ln_in_w = (const float*)d_in[3];
    const float* ln_in_b = (const float*)d_in[4];
    const float* ln_s_w  = (const float*)d_in[5];
    const float* ln_s_b  = (const float*)d_in[6];
    const float* Wq      = (const float*)d_in[7];
    const float* Wk      = (const float*)d_in[8];
    const float* Wv      = (const float*)d_in[9];
    const float* Wc      = (const float*)d_in[10];
    const float* Wih     = (const float*)d_in[11];
    const float* Whh     = (const float*)d_in[12];
    const float* bih     = (const float*)d_in[13];
    const float* bhh     = (const float*)d_in[14];
    const float* lnmw    = (const float*)d_in[15];
    const float* lnmb    = (const float*)d_in[16];
    const float* w1      = (const float*)d_in[17];
    const float* b1      = (const float*)d_in[18];
    const float* w2      = (const float*)d_in[19];
    const float* b2      = (const float*)d_in[20];
    float* out = (float*)d_out;

    cudaFuncSetAttribute(k_gemm_kv_mma, cudaFuncAttributeMaxDynamicSharedMemorySize, SM_TOTAL);
    cudaFuncSetAttribute(k_attn, cudaFuncAttributeMaxDynamicSharedMemorySize, AT_SMEM);

    k_init_slots<<<256, 256>>>(mu, lsig);
    k_prep_w<<<512, 256>>>(Wk, Wv);
    k_ln_in<<<BATCH * NTOK / 8, 256>>>(inputs, ln_in_w, ln_in_b);
    k_gemm_kv_mma<<<dim3(4, BATCH * NTOK / 128), 256, SM_TOTAL>>>();

    for (int it = 0; it < ITERS; it++) {
        k_slot_q<<<BATCH * SLOTS, 256>>>(Wq, ln_s_w, ln_s_b);
        k_attn<<<dim3(SPLIT, HEADS, BATCH), 256, AT_SMEM>>>();
        k_tail<<<BATCH * SLOTS / 2, 256>>>(Wc, Wih, Whh, bih, bhh,
                                           lnmw, lnmb, w1, b1, w2, b2,
                                           out, it == ITERS - 1 ? 1 : 0);
    }
}